// round 2
// baseline (speedup 1.0000x reference)
#include <cuda_runtime.h>
#include <math.h>

#define B_ 4
#define HW_ 65536
#define NTOK (B_*HW_)      // 262144 tokens
#define DIM_ 128
#define HEADS_ 4

// ---------------- scratch (device globals; no allocations allowed) ----------
__device__ float g_q[(size_t)NTOK*DIM_];
__device__ float g_k[(size_t)NTOK*DIM_];
__device__ float g_v[(size_t)NTOK*DIM_];
__device__ float g_attn[B_*HEADS_*32*32];
__device__ float g_attn_sm[B_*HEADS_*32*32];
__device__ float g_ssq[B_*HEADS_*32];
__device__ float g_ssk[B_*HEADS_*32];
__device__ float g_M[B_*DIM_*DIM_];

// ---------------- zero accumulators (graph-replay safe) ---------------------
__global__ void zero_kernel() {
    int i = blockIdx.x*blockDim.x + threadIdx.x;
    if (i < B_*HEADS_*32*32) g_attn[i] = 0.f;
    if (i < B_*HEADS_*32) { g_ssq[i] = 0.f; g_ssk[i] = 0.f; }
}

// ---------------- 128x128 (tokens x outs) x K=128 fp32 GEMM tile ------------
__device__ __forceinline__ void gemm_body(const float* __restrict__ X,
                                          const float* __restrict__ W,
                                          float* __restrict__ Out,
                                          const float* __restrict__ bias)
{
    __shared__ float As[16][128];   // [k][token]
    __shared__ float Bs[16][128];   // [k][out]
    int tid = threadIdx.x;
    int tr = (tid >> 4) << 3;       // token offset (16 groups of 8)
    int tc = (tid & 15) << 3;       // out offset
    float acc[8][8];
#pragma unroll
    for (int i = 0; i < 8; i++)
#pragma unroll
        for (int j = 0; j < 8; j++) acc[i][j] = 0.f;

    for (int k0 = 0; k0 < 128; k0 += 16) {
        {
            int t  = tid >> 1;
            int kb = (tid & 1) << 3;
            float4 x0 = *(const float4*)(X + (size_t)t*128 + k0 + kb);
            float4 x1 = *(const float4*)(X + (size_t)t*128 + k0 + kb + 4);
            As[kb+0][t]=x0.x; As[kb+1][t]=x0.y; As[kb+2][t]=x0.z; As[kb+3][t]=x0.w;
            As[kb+4][t]=x1.x; As[kb+5][t]=x1.y; As[kb+6][t]=x1.z; As[kb+7][t]=x1.w;
            int kk = tid >> 4;
            int oc = (tid & 15) << 3;
            *(float4*)&Bs[kk][oc]   = *(const float4*)(W + (size_t)(k0+kk)*128 + oc);
            *(float4*)&Bs[kk][oc+4] = *(const float4*)(W + (size_t)(k0+kk)*128 + oc + 4);
        }
        __syncthreads();
#pragma unroll
        for (int kk = 0; kk < 16; kk++) {
            float a[8], bb[8];
            *(float4*)&a[0]  = *(float4*)&As[kk][tr];
            *(float4*)&a[4]  = *(float4*)&As[kk][tr+4];
            *(float4*)&bb[0] = *(float4*)&Bs[kk][tc];
            *(float4*)&bb[4] = *(float4*)&Bs[kk][tc+4];
#pragma unroll
            for (int i = 0; i < 8; i++)
#pragma unroll
                for (int j = 0; j < 8; j++) acc[i][j] += a[i]*bb[j];
        }
        __syncthreads();
    }
    float bf[8];
#pragma unroll
    for (int j = 0; j < 8; j++) bf[j] = bias ? bias[tc+j] : 0.f;
#pragma unroll
    for (int i = 0; i < 8; i++) {
        float ov[8];
#pragma unroll
        for (int j = 0; j < 8; j++) ov[j] = acc[i][j] + bf[j];
        *(float4*)(Out + (size_t)(tr+i)*128 + tc)     = *(float4*)&ov[0];
        *(float4*)(Out + (size_t)(tr+i)*128 + tc + 4) = *(float4*)&ov[4];
    }
}

__global__ void __launch_bounds__(256) qkv_kernel(const float* __restrict__ x,
                                                  const float* __restrict__ Wq,
                                                  const float* __restrict__ Wk,
                                                  const float* __restrict__ Wv)
{
    int wsel = blockIdx.y;
    const float* W = (wsel == 0) ? Wq : ((wsel == 1) ? Wk : Wv);
    float* out = (wsel == 0) ? g_q : ((wsel == 1) ? g_k : g_v);
    size_t tok0 = (size_t)blockIdx.x * 128;
    gemm_body(x + tok0*128, W, out + tok0*128, nullptr);
}

__global__ void __launch_bounds__(256) vm_kernel(const float* __restrict__ bproj,
                                                 float* __restrict__ out)
{
    size_t tok0 = (size_t)blockIdx.x * 128;
    int b = blockIdx.x >> 9;   // 512 tiles per batch
    gemm_body(g_v + tok0*128, g_M + (size_t)b*DIM_*DIM_, out + tok0*128, bproj);
}

// ---------------- attn accumulation: attn[d,e] = sum_n k[d,n] q[e,n] --------
#define NCHUNK 16
__global__ void __launch_bounds__(256) attn_kernel()
{
    __shared__ float qs[64*33];
    __shared__ float ks[64*33];
    int b = blockIdx.z, h = blockIdx.y;
    int n0 = blockIdx.x * (HW_ / NCHUNK);
    int tid = threadIdx.x;
    int d_ = tid >> 3;              // 0..31
    int e4 = (tid & 7) << 2;        // 0..28
    // sumsq role
    int which = tid >> 7;           // 0:k 1:q
    int sd    = (tid & 127) & 31;
    int st0   = (((tid & 127) >> 5) << 4);  // 0,16,32,48
    float acc[4] = {0.f,0.f,0.f,0.f};
    float ssacc = 0.f;

    for (int sub = 0; sub < (HW_/NCHUNK)/64; sub++) {
        int t0 = n0 + sub*64;
        {
            int r  = tid >> 2;
            int c8 = (tid & 3) << 3;
            size_t base = ((size_t)(b*HW_ + t0 + r))*128 + h*32 + c8;
            float4 a0 = *(const float4*)(g_q + base);
            float4 a1 = *(const float4*)(g_q + base + 4);
            qs[r*33+c8+0]=a0.x; qs[r*33+c8+1]=a0.y; qs[r*33+c8+2]=a0.z; qs[r*33+c8+3]=a0.w;
            qs[r*33+c8+4]=a1.x; qs[r*33+c8+5]=a1.y; qs[r*33+c8+6]=a1.z; qs[r*33+c8+7]=a1.w;
            float4 b0 = *(const float4*)(g_k + base);
            float4 b1 = *(const float4*)(g_k + base + 4);
            ks[r*33+c8+0]=b0.x; ks[r*33+c8+1]=b0.y; ks[r*33+c8+2]=b0.z; ks[r*33+c8+3]=b0.w;
            ks[r*33+c8+4]=b1.x; ks[r*33+c8+5]=b1.y; ks[r*33+c8+6]=b1.z; ks[r*33+c8+7]=b1.w;
        }
        __syncthreads();
#pragma unroll 4
        for (int t = 0; t < 64; t++) {
            float kd = ks[t*33 + d_];
            acc[0] += kd * qs[t*33 + e4 + 0];
            acc[1] += kd * qs[t*33 + e4 + 1];
            acc[2] += kd * qs[t*33 + e4 + 2];
            acc[3] += kd * qs[t*33 + e4 + 3];
        }
        const float* src = which ? qs : ks;
#pragma unroll
        for (int tt = 0; tt < 16; tt++) {
            float v = src[(st0+tt)*33 + sd];
            ssacc += v*v;
        }
        __syncthreads();
    }
    int bh = b*HEADS_ + h;
#pragma unroll
    for (int j = 0; j < 4; j++)
        atomicAdd(&g_attn[(bh*32 + d_)*32 + e4 + j], acc[j]);
    atomicAdd(which ? &g_ssq[bh*32 + sd] : &g_ssk[bh*32 + sd], ssacc);
}

// ---------------- scale + softmax over e ------------------------------------
__global__ void __launch_bounds__(1024) softmax_kernel(const float* __restrict__ rescale)
{
    int bh = blockIdx.x;
    int h = bh & 3;
    int tid = threadIdx.x;
    int d = tid >> 5, e = tid & 31;
    float nk = fmaxf(sqrtf(g_ssk[bh*32 + d]), 1e-12f);
    float nq = fmaxf(sqrtf(g_ssq[bh*32 + e]), 1e-12f);
    float val = g_attn[bh*1024 + d*32 + e] * rescale[h] / (nk*nq);
    float m = val;
#pragma unroll
    for (int off = 16; off > 0; off >>= 1) m = fmaxf(m, __shfl_xor_sync(0xffffffffu, m, off));
    float ex = expf(val - m);
    float s = ex;
#pragma unroll
    for (int off = 16; off > 0; off >>= 1) s += __shfl_xor_sync(0xffffffffu, s, off);
    g_attn_sm[bh*1024 + d*32 + e] = ex / s;
}

// ---------------- M[b] = blockdiag(softmax attn) @ Wproj --------------------
__global__ void __launch_bounds__(256) m_kernel(const float* __restrict__ Wproj)
{
    __shared__ float as[32*33];
    __shared__ float wp[32*128];
    int bh = blockIdx.x;
    int b = bh >> 2, h = bh & 3;
    int tid = threadIdx.x;
    for (int i = tid; i < 1024; i += 256) {
        int d = i >> 5, e = i & 31;
        as[d*33 + e] = g_attn_sm[bh*1024 + i];
    }
    for (int i = tid; i < 1024; i += 256)
        ((float4*)wp)[i] = ((const float4*)(Wproj + (size_t)h*32*128))[i];
    __syncthreads();
    int c  = tid & 127;
    int eg = tid >> 7;
    for (int ee = 0; ee < 16; ee++) {
        int e = eg*16 + ee;
        float a = 0.f;
#pragma unroll
        for (int d = 0; d < 32; d++) a += as[d*33 + e] * wp[d*128 + c];
        g_M[(size_t)b*16384 + (h*32 + e)*128 + c] = a;
    }
}

// ---------------- fused Gabor (separable) + GELU + pointwise ----------------
// smem floats: vt 14*14*32=6272 | ts 112*33=3696 | gs 64*33=2112 | pws 128*33=4224
#define SM_TS  6272
#define SM_GS  (6272+3696)
#define SM_PW  (6272+3696+2112)
#define SM_TOTF (6272+3696+2112+4224)

__global__ void __launch_bounds__(256) gabor_kernel(const float* __restrict__ v_unused,
                                                    const float* __restrict__ dw_w,
                                                    const float* __restrict__ dw_b,
                                                    const float* __restrict__ pw_w,
                                                    const float* __restrict__ pw_b,
                                                    float* __restrict__ out)
{
    extern __shared__ float sm[];
    float* vt  = sm;
    float* ts  = sm + SM_TS;
    float* gs  = sm + SM_GS;
    float* pws = sm + SM_PW;

    int b  = blockIdx.z;
    int y0 = blockIdx.y << 3;
    int x0 = blockIdx.x << 3;
    int tid = threadIdx.x;
    int pg = tid & 15;      // pixel group (4 pixels)
    int og = tid >> 4;      // out group (8 outs)

    float acc[4][8];
#pragma unroll
    for (int p = 0; p < 4; p++)
#pragma unroll
        for (int o = 0; o < 8; o++) acc[p][o] = 0.f;

    for (int cg = 0; cg < 4; cg++) {
        int c0 = cg << 5;
        __syncthreads();
        // load v halo tile [14][14][32]
        {
            int c = tid & 31;
            for (int p = tid >> 5; p < 196; p += 8) {
                int row = p / 14, col = p % 14;
                int gy = y0 - 3 + row, gx = x0 - 3 + col;
                float val = 0.f;
                if ((unsigned)gy < 256u && (unsigned)gx < 256u)
                    val = g_v[((size_t)(b*HW_ + gy*256 + gx))*128 + c0 + c];
                vt[(row*14 + col)*32 + c] = val;
            }
        }
        for (int s = 0; s < 4; s++) {
            __syncthreads();
            // horizontal pass (separable col factor = dw_w row i=4)
            {
                float Bf[7];
#pragma unroll
                for (int j = 0; j < 7; j++) Bf[j] = dw_w[s*49 + 28 + j];
                int c = tid & 31;
                for (int rx = tid >> 5; rx < 112; rx += 8) {
                    int row = rx >> 3, xx = rx & 7;
                    float sum = 0.f;
#pragma unroll
                    for (int j = 0; j < 7; j++) sum += Bf[j]*vt[(row*14 + xx + j)*32 + c];
                    ts[rx*33 + c] = sum;
                }
            }
            // stage pointwise weights pws[o][cc] = pw_w[o, (c0+cc)*4+s]
            {
                int o = tid >> 1, cc0 = (tid & 1) << 4;
                for (int q = 0; q < 16; q++) {
                    int cc = cc0 + q;
                    pws[o*33 + cc] = pw_w[(size_t)o*512 + (c0+cc)*4 + s];
                }
            }
            __syncthreads();
            // vertical pass (row factor = dw_w col j=4) + bias + exact GELU
            {
                float Af[7];
#pragma unroll
                for (int i = 0; i < 7; i++) Af[i] = dw_w[s*49 + i*7 + 4];
                int c = tid & 31;
                float bias = dw_b[(c0+c)*4 + s];
                for (int yx = tid >> 5; yx < 64; yx += 8) {
                    int y = yx >> 3, xx = yx & 7;
                    float sum = bias;
#pragma unroll
                    for (int i = 0; i < 7; i++) sum += Af[i]*ts[((y+i)*8 + xx)*33 + c];
                    float g = 0.5f*sum*(1.f + erff(sum*0.70710678118654752f));
                    gs[yx*33 + c] = g;
                }
            }
            __syncthreads();
            // pointwise partial: acc[p][o] += pw[o][cc]*g[pix][cc]
#pragma unroll 2
            for (int cc = 0; cc < 32; cc++) {
                float gv[4];
#pragma unroll
                for (int p = 0; p < 4; p++) gv[p] = gs[(pg*4 + p)*33 + cc];
                float pv[8];
#pragma unroll
                for (int o = 0; o < 8; o++) pv[o] = pws[(og*8 + o)*33 + cc];
#pragma unroll
                for (int p = 0; p < 4; p++)
#pragma unroll
                    for (int o = 0; o < 8; o++) acc[p][o] += gv[p]*pv[o];
            }
        }
    }
    // out += out_p (+ pw_b); each (pixel,out) owned by exactly one block
    float pb[8];
#pragma unroll
    for (int o = 0; o < 8; o++) pb[o] = pw_b[og*8 + o];
#pragma unroll
    for (int p = 0; p < 4; p++) {
        int pix = pg*4 + p;
        int y = pix >> 3, xx = pix & 7;
        size_t base = ((size_t)(b*HW_ + (y0+y)*256 + x0+xx))*128 + og*8;
        float4 o0 = *(float4*)(out + base);
        float4 o1 = *(float4*)(out + base + 4);
        o0.x += acc[p][0] + pb[0]; o0.y += acc[p][1] + pb[1];
        o0.z += acc[p][2] + pb[2]; o0.w += acc[p][3] + pb[3];
        o1.x += acc[p][4] + pb[4]; o1.y += acc[p][5] + pb[5];
        o1.z += acc[p][6] + pb[6]; o1.w += acc[p][7] + pb[7];
        *(float4*)(out + base)     = o0;
        *(float4*)(out + base + 4) = o1;
    }
}

// ---------------------------------------------------------------------------
extern "C" void kernel_launch(void* const* d_in, const int* in_sizes, int n_in,
                              void* d_out, int out_size)
{
    const float* x       = (const float*)d_in[0];
    const float* Wq      = (const float*)d_in[1];
    const float* Wk      = (const float*)d_in[2];
    const float* Wv      = (const float*)d_in[3];
    const float* rescale = (const float*)d_in[4];
    const float* Wproj   = (const float*)d_in[5];
    const float* bproj   = (const float*)d_in[6];
    const float* dw_w    = (const float*)d_in[7];
    const float* dw_b    = (const float*)d_in[8];
    const float* pw_w    = (const float*)d_in[9];
    const float* pw_b    = (const float*)d_in[10];
    float* out = (float*)d_out;

    zero_kernel<<<64, 256>>>();
    qkv_kernel<<<dim3(NTOK/128, 3), 256>>>(x, Wq, Wk, Wv);
    attn_kernel<<<dim3(NCHUNK, HEADS_, B_), 256>>>();
    softmax_kernel<<<B_*HEADS_, 1024>>>(rescale);
    m_kernel<<<B_*HEADS_, 256>>>(Wproj);
    vm_kernel<<<NTOK/128, 256>>>(bproj, out);

    cudaFuncSetAttribute(gabor_kernel, cudaFuncAttributeMaxDynamicSharedMemorySize,
                         SM_TOTF * (int)sizeof(float));
    gabor_kernel<<<dim3(32, 32, B_), 256, SM_TOTF * sizeof(float)>>>(
        nullptr, dw_w, dw_b, pw_w, pw_b, out);
}

// round 3
// speedup vs baseline: 1.4693x; 1.4693x over previous
#include <cuda_runtime.h>
#include <math.h>
#include <stdint.h>

#define B_ 4
#define HW_ 65536
#define NTOK (B_*HW_)      // 262144 tokens
#define DIM_ 128
#define HEADS_ 4

// ---------------- scratch (device globals; no allocations allowed) ----------
__device__ float g_q[(size_t)NTOK*DIM_];
__device__ float g_k[(size_t)NTOK*DIM_];
__device__ float g_v[(size_t)NTOK*DIM_];
__device__ float g_attn[B_*HEADS_*32*32];
__device__ float g_attn_sm[B_*HEADS_*32*32];
__device__ float g_ssq[B_*HEADS_*32];
__device__ float g_ssk[B_*HEADS_*32];
__device__ float g_M[B_*DIM_*DIM_];

// ---------------- tf32 helpers ----------------------------------------------
__device__ __forceinline__ uint32_t f2tf(float f) {
    uint32_t u; asm("cvt.rna.tf32.f32 %0, %1;" : "=r"(u) : "f"(f)); return u;
}
__device__ __forceinline__ void mma8(float* c,
                                     uint32_t a0, uint32_t a1, uint32_t a2, uint32_t a3,
                                     uint32_t b0, uint32_t b1) {
    asm volatile(
        "mma.sync.aligned.m16n8k8.row.col.f32.tf32.tf32.f32 "
        "{%0,%1,%2,%3},{%4,%5,%6,%7},{%8,%9},{%0,%1,%2,%3};"
        : "+f"(c[0]), "+f"(c[1]), "+f"(c[2]), "+f"(c[3])
        : "r"(a0), "r"(a1), "r"(a2), "r"(a3), "r"(b0), "r"(b1));
}

// ---------------- zero accumulators (graph-replay safe) ---------------------
__global__ void zero_kernel() {
    int i = blockIdx.x*blockDim.x + threadIdx.x;
    if (i < B_*HEADS_*32*32) g_attn[i] = 0.f;
    if (i < B_*HEADS_*32) { g_ssq[i] = 0.f; g_ssk[i] = 0.f; }
}

// ---------------- 128x128xK=128 tf32 MMA GEMM tile ---------------------------
#define LDA 132
__device__ __forceinline__ void gemm_mma(const float* __restrict__ X,
                                         const float* __restrict__ W,
                                         float* __restrict__ Out,
                                         const float* __restrict__ bias)
{
    __shared__ uint32_t As[16*LDA];   // [k][token]
    __shared__ uint32_t Bs[16*LDA];   // [k][out]
    int tid = threadIdx.x;
    int lane = tid & 31, warp = tid >> 5;
    int wm = (warp & 3) * 32;   // token base
    int wn = (warp >> 2) * 64;  // out base
    float acc[2][8][4];
#pragma unroll
    for (int mt = 0; mt < 2; mt++)
#pragma unroll
        for (int nt = 0; nt < 8; nt++)
#pragma unroll
            for (int r = 0; r < 4; r++) acc[mt][nt][r] = 0.f;

    for (int k0 = 0; k0 < 128; k0 += 16) {
        {   // stage A transposed
            int t  = tid >> 1;
            int kb = (tid & 1) << 3;
            float4 x0 = *(const float4*)(X + (size_t)t*128 + k0 + kb);
            float4 x1 = *(const float4*)(X + (size_t)t*128 + k0 + kb + 4);
            As[(kb+0)*LDA + t] = f2tf(x0.x); As[(kb+1)*LDA + t] = f2tf(x0.y);
            As[(kb+2)*LDA + t] = f2tf(x0.z); As[(kb+3)*LDA + t] = f2tf(x0.w);
            As[(kb+4)*LDA + t] = f2tf(x1.x); As[(kb+5)*LDA + t] = f2tf(x1.y);
            As[(kb+6)*LDA + t] = f2tf(x1.z); As[(kb+7)*LDA + t] = f2tf(x1.w);
            // stage B direct
            int kk = tid >> 4;
            int n0 = (tid & 15) << 3;
            float4 w0 = *(const float4*)(W + (size_t)(k0+kk)*128 + n0);
            float4 w1 = *(const float4*)(W + (size_t)(k0+kk)*128 + n0 + 4);
            Bs[kk*LDA + n0+0] = f2tf(w0.x); Bs[kk*LDA + n0+1] = f2tf(w0.y);
            Bs[kk*LDA + n0+2] = f2tf(w0.z); Bs[kk*LDA + n0+3] = f2tf(w0.w);
            Bs[kk*LDA + n0+4] = f2tf(w1.x); Bs[kk*LDA + n0+5] = f2tf(w1.y);
            Bs[kk*LDA + n0+6] = f2tf(w1.z); Bs[kk*LDA + n0+7] = f2tf(w1.w);
        }
        __syncthreads();
#pragma unroll
        for (int ks = 0; ks < 16; ks += 8) {
            int ar = ks + (lane & 3);
            int ac = wm + (lane >> 2);
            uint32_t a[2][4];
#pragma unroll
            for (int mt = 0; mt < 2; mt++) {
                int base = ac + mt*16;
                a[mt][0] = As[ar*LDA + base];
                a[mt][1] = As[ar*LDA + base + 8];
                a[mt][2] = As[(ar+4)*LDA + base];
                a[mt][3] = As[(ar+4)*LDA + base + 8];
            }
            uint32_t b[8][2];
            int bc = wn + (lane >> 2);
#pragma unroll
            for (int nt = 0; nt < 8; nt++) {
                b[nt][0] = Bs[ar*LDA + bc + nt*8];
                b[nt][1] = Bs[(ar+4)*LDA + bc + nt*8];
            }
#pragma unroll
            for (int mt = 0; mt < 2; mt++)
#pragma unroll
                for (int nt = 0; nt < 8; nt++)
                    mma8(acc[mt][nt], a[mt][0], a[mt][1], a[mt][2], a[mt][3],
                         b[nt][0], b[nt][1]);
        }
        __syncthreads();
    }
    // epilogue
    int row0 = wm + (lane >> 2);
    int col0 = wn + (lane & 3)*2;
#pragma unroll
    for (int mt = 0; mt < 2; mt++) {
#pragma unroll
        for (int nt = 0; nt < 8; nt++) {
            int r = row0 + mt*16;
            int c = col0 + nt*8;
            float b0 = bias ? bias[c]   : 0.f;
            float b1 = bias ? bias[c+1] : 0.f;
            float2 v0 = make_float2(acc[mt][nt][0] + b0, acc[mt][nt][1] + b1);
            float2 v1 = make_float2(acc[mt][nt][2] + b0, acc[mt][nt][3] + b1);
            *(float2*)(Out + (size_t)r*128 + c)     = v0;
            *(float2*)(Out + (size_t)(r+8)*128 + c) = v1;
        }
    }
}

__global__ void __launch_bounds__(256) qkv_kernel(const float* __restrict__ x,
                                                  const float* __restrict__ Wq,
                                                  const float* __restrict__ Wk,
                                                  const float* __restrict__ Wv)
{
    int wsel = blockIdx.x;  // x fastest -> 3 blocks sharing X tile are adjacent
    const float* W = (wsel == 0) ? Wq : ((wsel == 1) ? Wk : Wv);
    float* out = (wsel == 0) ? g_q : ((wsel == 1) ? g_k : g_v);
    size_t tok0 = (size_t)blockIdx.y * 128;
    gemm_mma(x + tok0*128, W, out + tok0*128, nullptr);
}

__global__ void __launch_bounds__(256) vm_kernel(const float* __restrict__ bproj,
                                                 float* __restrict__ out)
{
    size_t tok0 = (size_t)blockIdx.x * 128;
    int b = blockIdx.x >> 9;   // 512 tiles per batch
    gemm_mma(g_v + tok0*128, g_M + (size_t)b*DIM_*DIM_, out + tok0*128, bproj);
}

// ---------------- attn accumulation via tf32 mma ----------------------------
// attn[d,e] = sum_n k[d,n] q[e,n]; 64-token tiles; warp w handles tokens w*8..w*8+7
#define NCHUNK 16
#define LQS 36
__global__ void __launch_bounds__(256) attn_kernel()
{
    __shared__ uint32_t qs[64*LQS];
    __shared__ uint32_t ks[64*LQS];
    int b = blockIdx.z, h = blockIdx.y;
    int n0 = blockIdx.x * (HW_ / NCHUNK);
    int tid = threadIdx.x;
    int lane = tid & 31, warp = tid >> 5;
    float acc[2][4][4];
#pragma unroll
    for (int mt = 0; mt < 2; mt++)
#pragma unroll
        for (int nt = 0; nt < 4; nt++)
#pragma unroll
            for (int r = 0; r < 4; r++) acc[mt][nt][r] = 0.f;
    float ssk_acc = 0.f, ssq_acc = 0.f;

    for (int sub = 0; sub < (HW_/NCHUNK)/64; sub++) {
        int t0 = n0 + sub*64;
        {
            int r  = tid >> 2;
            int c8 = (tid & 3) << 3;
            size_t base = ((size_t)(b*HW_ + t0 + r))*128 + h*32 + c8;
            float4 a0 = *(const float4*)(g_q + base);
            float4 a1 = *(const float4*)(g_q + base + 4);
            qs[r*LQS+c8+0]=f2tf(a0.x); qs[r*LQS+c8+1]=f2tf(a0.y);
            qs[r*LQS+c8+2]=f2tf(a0.z); qs[r*LQS+c8+3]=f2tf(a0.w);
            qs[r*LQS+c8+4]=f2tf(a1.x); qs[r*LQS+c8+5]=f2tf(a1.y);
            qs[r*LQS+c8+6]=f2tf(a1.z); qs[r*LQS+c8+7]=f2tf(a1.w);
            float4 b0 = *(const float4*)(g_k + base);
            float4 b1 = *(const float4*)(g_k + base + 4);
            ks[r*LQS+c8+0]=f2tf(b0.x); ks[r*LQS+c8+1]=f2tf(b0.y);
            ks[r*LQS+c8+2]=f2tf(b0.z); ks[r*LQS+c8+3]=f2tf(b0.w);
            ks[r*LQS+c8+4]=f2tf(b1.x); ks[r*LQS+c8+5]=f2tf(b1.y);
            ks[r*LQS+c8+6]=f2tf(b1.z); ks[r*LQS+c8+7]=f2tf(b1.w);
        }
        __syncthreads();
        int kt = warp * 8;
        int ar = kt + (lane & 3);     // token row (a0/b0)
        int dq = lane >> 2;
        uint32_t a[2][4];
#pragma unroll
        for (int mt = 0; mt < 2; mt++) {
            int d = dq + mt*16;
            a[mt][0] = ks[ar*LQS + d];
            a[mt][1] = ks[ar*LQS + d + 8];
            a[mt][2] = ks[(ar+4)*LQS + d];
            a[mt][3] = ks[(ar+4)*LQS + d + 8];
        }
#pragma unroll
        for (int nt = 0; nt < 4; nt++) {
            int e = dq + nt*8;
            uint32_t b0 = qs[ar*LQS + e];
            uint32_t b1 = qs[(ar+4)*LQS + e];
#pragma unroll
            for (int mt = 0; mt < 2; mt++)
                mma8(acc[mt][nt], a[mt][0], a[mt][1], a[mt][2], a[mt][3], b0, b1);
        }
        // sum of squares over this warp's 8 tokens, ch = lane
#pragma unroll
        for (int tt = 0; tt < 8; tt++) {
            float kv = __uint_as_float(ks[(kt+tt)*LQS + lane]);
            float qv = __uint_as_float(qs[(kt+tt)*LQS + lane]);
            ssk_acc += kv*kv;
            ssq_acc += qv*qv;
        }
        __syncthreads();
    }
    int bh = b*HEADS_ + h;
    int dq = lane >> 2;
    int e0 = (lane & 3)*2;
#pragma unroll
    for (int mt = 0; mt < 2; mt++) {
#pragma unroll
        for (int nt = 0; nt < 4; nt++) {
            int d = dq + mt*16;
            int e = e0 + nt*8;
            atomicAdd(&g_attn[(bh*32 + d)*32 + e],       acc[mt][nt][0]);
            atomicAdd(&g_attn[(bh*32 + d)*32 + e + 1],   acc[mt][nt][1]);
            atomicAdd(&g_attn[(bh*32 + d+8)*32 + e],     acc[mt][nt][2]);
            atomicAdd(&g_attn[(bh*32 + d+8)*32 + e + 1], acc[mt][nt][3]);
        }
    }
    atomicAdd(&g_ssk[bh*32 + lane], ssk_acc);
    atomicAdd(&g_ssq[bh*32 + lane], ssq_acc);
}

// ---------------- scale + softmax over e ------------------------------------
__global__ void __launch_bounds__(1024) softmax_kernel(const float* __restrict__ rescale)
{
    int bh = blockIdx.x;
    int h = bh & 3;
    int tid = threadIdx.x;
    int d = tid >> 5, e = tid & 31;
    float nk = fmaxf(sqrtf(g_ssk[bh*32 + d]), 1e-12f);
    float nq = fmaxf(sqrtf(g_ssq[bh*32 + e]), 1e-12f);
    float val = g_attn[bh*1024 + d*32 + e] * rescale[h] / (nk*nq);
    float m = val;
#pragma unroll
    for (int off = 16; off > 0; off >>= 1) m = fmaxf(m, __shfl_xor_sync(0xffffffffu, m, off));
    float ex = expf(val - m);
    float s = ex;
#pragma unroll
    for (int off = 16; off > 0; off >>= 1) s += __shfl_xor_sync(0xffffffffu, s, off);
    g_attn_sm[bh*1024 + d*32 + e] = ex / s;
}

// ---------------- M[b] = blockdiag(softmax attn) @ Wproj --------------------
__global__ void __launch_bounds__(256) m_kernel(const float* __restrict__ Wproj)
{
    __shared__ float as[32*33];
    __shared__ float wp[32*128];
    int bh = blockIdx.x;
    int b = bh >> 2, h = bh & 3;
    int tid = threadIdx.x;
    for (int i = tid; i < 1024; i += 256) {
        int d = i >> 5, e = i & 31;
        as[d*33 + e] = g_attn_sm[bh*1024 + i];
    }
    for (int i = tid; i < 1024; i += 256)
        ((float4*)wp)[i] = ((const float4*)(Wproj + (size_t)h*32*128))[i];
    __syncthreads();
    int c  = tid & 127;
    int eg = tid >> 7;
    for (int ee = 0; ee < 16; ee++) {
        int e = eg*16 + ee;
        float a = 0.f;
#pragma unroll
        for (int d = 0; d < 32; d++) a += as[d*33 + e] * wp[d*128 + c];
        g_M[(size_t)b*16384 + (h*32 + e)*128 + c] = a;
    }
}

// ---------------- fused Gabor (separable) + GELU + pointwise (tf32 mma) -----
// floats: vt 14*14*32=6272 | ts 112*33=3696 ; u32: gs 64*36=2304 | pws 128*36=4608
#define GB_VT 6272
#define GB_TS 3696
#define GB_GS (64*36)
#define GB_PW (128*36)
#define GB_TOT (GB_VT + GB_TS + GB_GS + GB_PW)

__global__ void __launch_bounds__(256) gabor_kernel(const float* __restrict__ dw_w,
                                                    const float* __restrict__ dw_b,
                                                    const float* __restrict__ pw_w,
                                                    const float* __restrict__ pw_b,
                                                    float* __restrict__ out)
{
    extern __shared__ float sm[];
    float* vt  = sm;
    float* ts  = sm + GB_VT;
    uint32_t* gs  = (uint32_t*)(sm + GB_VT + GB_TS);
    uint32_t* pws = gs + GB_GS;

    int b  = blockIdx.z;
    int y0 = blockIdx.y << 3;
    int x0 = blockIdx.x << 3;
    int tid = threadIdx.x;
    int lane = tid & 31, warp = tid >> 5;
    int wn = warp * 16;      // out-column base for this warp

    float acc[4][2][4];      // 4 pix-tiles x 2 out-tiles x frag
#pragma unroll
    for (int mt = 0; mt < 4; mt++)
#pragma unroll
        for (int nt = 0; nt < 2; nt++)
#pragma unroll
            for (int r = 0; r < 4; r++) acc[mt][nt][r] = 0.f;

    for (int cg = 0; cg < 4; cg++) {
        int c0 = cg << 5;
        __syncthreads();
        // load v halo tile [14][14][32]
        {
            int c = tid & 31;
            for (int p = tid >> 5; p < 196; p += 8) {
                int row = p / 14, col = p % 14;
                int gy = y0 - 3 + row, gx = x0 - 3 + col;
                float val = 0.f;
                if ((unsigned)gy < 256u && (unsigned)gx < 256u)
                    val = g_v[((size_t)(b*HW_ + gy*256 + gx))*128 + c0 + c];
                vt[(row*14 + col)*32 + c] = val;
            }
        }
        for (int s = 0; s < 4; s++) {
            __syncthreads();
            // horizontal pass
            {
                float Bf[7];
#pragma unroll
                for (int j = 0; j < 7; j++) Bf[j] = dw_w[s*49 + 28 + j];
                int c = tid & 31;
                for (int rx = tid >> 5; rx < 112; rx += 8) {
                    int row = rx >> 3, xx = rx & 7;
                    float sum = 0.f;
#pragma unroll
                    for (int j = 0; j < 7; j++) sum += Bf[j]*vt[(row*14 + xx + j)*32 + c];
                    ts[rx*33 + c] = sum;
                }
            }
            // stage pointwise weights as tf32: pws[o][cc] = pw_w[o, (c0+cc)*4+s]
            {
                int o = tid >> 1, cc0 = (tid & 1) << 4;
                for (int q = 0; q < 16; q++) {
                    int cc = cc0 + q;
                    pws[o*36 + cc] = f2tf(pw_w[(size_t)o*512 + (c0+cc)*4 + s]);
                }
            }
            __syncthreads();
            // vertical pass + bias + exact GELU -> gs (tf32)
            {
                float Af[7];
#pragma unroll
                for (int i = 0; i < 7; i++) Af[i] = dw_w[s*49 + i*7 + 4];
                int c = tid & 31;
                float bias = dw_b[(c0+c)*4 + s];
                for (int yx = tid >> 5; yx < 64; yx += 8) {
                    int y = yx >> 3, xx = yx & 7;
                    float sum = bias;
#pragma unroll
                    for (int i = 0; i < 7; i++) sum += Af[i]*ts[((y+i)*8 + xx)*33 + c];
                    float g = 0.5f*sum*(1.f + erff(sum*0.70710678118654752f));
                    gs[yx*36 + c] = f2tf(g);
                }
            }
            __syncthreads();
            // pointwise via mma: Out[64 pix][128 out] += g[64][32] * pw^T
#pragma unroll
            for (int ks = 0; ks < 32; ks += 8) {
                int ar = ks + (lane & 3);
                int pq = lane >> 2;
                uint32_t a[4][4];
#pragma unroll
                for (int mt = 0; mt < 4; mt++) {
                    int p = mt*16 + pq;
                    a[mt][0] = gs[p*36 + ar];
                    a[mt][1] = gs[(p+8)*36 + ar];
                    a[mt][2] = gs[p*36 + ar + 4];
                    a[mt][3] = gs[(p+8)*36 + ar + 4];
                }
#pragma unroll
                for (int nt = 0; nt < 2; nt++) {
                    int o = wn + nt*8 + pq;
                    uint32_t b0 = pws[o*36 + ar];
                    uint32_t b1 = pws[o*36 + ar + 4];
#pragma unroll
                    for (int mt = 0; mt < 4; mt++)
                        mma8(acc[mt][nt], a[mt][0], a[mt][1], a[mt][2], a[mt][3], b0, b1);
                }
            }
        }
    }
    // epilogue: out += acc + pw_b (each (pixel,out) owned by one thread)
    int pq = lane >> 2;
    int e0 = (lane & 3)*2;
#pragma unroll
    for (int mt = 0; mt < 4; mt++) {
#pragma unroll
        for (int nt = 0; nt < 2; nt++) {
            int c = wn + nt*8 + e0;
            float pb0 = pw_b[c], pb1 = pw_b[c+1];
#pragma unroll
            for (int half = 0; half < 2; half++) {
                int pix = mt*16 + pq + half*8;
                int y = pix >> 3, xx = pix & 7;
                size_t base = ((size_t)(b*HW_ + (y0+y)*256 + x0+xx))*128 + c;
                float2 o0 = *(float2*)(out + base);
                o0.x += acc[mt][nt][half*2+0] + pb0;
                o0.y += acc[mt][nt][half*2+1] + pb1;
                *(float2*)(out + base) = o0;
            }
        }
    }
}

// ---------------------------------------------------------------------------
extern "C" void kernel_launch(void* const* d_in, const int* in_sizes, int n_in,
                              void* d_out, int out_size)
{
    const float* x       = (const float*)d_in[0];
    const float* Wq      = (const float*)d_in[1];
    const float* Wk      = (const float*)d_in[2];
    const float* Wv      = (const float*)d_in[3];
    const float* rescale = (const float*)d_in[4];
    const float* Wproj   = (const float*)d_in[5];
    const float* bproj   = (const float*)d_in[6];
    const float* dw_w    = (const float*)d_in[7];
    const float* dw_b    = (const float*)d_in[8];
    const float* pw_w    = (const float*)d_in[9];
    const float* pw_b    = (const float*)d_in[10];
    float* out = (float*)d_out;

    zero_kernel<<<64, 256>>>();
    qkv_kernel<<<dim3(3, NTOK/128), 256>>>(x, Wq, Wk, Wv);
    attn_kernel<<<dim3(NCHUNK, HEADS_, B_), 256>>>();
    softmax_kernel<<<B_*HEADS_, 1024>>>(rescale);
    m_kernel<<<B_*HEADS_, 256>>>(Wproj);
    vm_kernel<<<NTOK/128, 256>>>(bproj, out);

    cudaFuncSetAttribute(gabor_kernel, cudaFuncAttributeMaxDynamicSharedMemorySize,
                         GB_TOT * (int)sizeof(float));
    gabor_kernel<<<dim3(32, 32, B_), 256, GB_TOT * sizeof(float)>>>(
        dw_w, dw_b, pw_w, pw_b, out);
}

// round 4
// speedup vs baseline: 1.4963x; 1.0184x over previous
#include <cuda_runtime.h>
#include <math.h>
#include <stdint.h>

#define B_ 4
#define HW_ 65536
#define NTOK (B_*HW_)      // 262144 tokens
#define DIM_ 128
#define HEADS_ 4

// ---------------- scratch (device globals; no allocations allowed) ----------
__device__ float g_q[(size_t)NTOK*DIM_];
__device__ float g_k[(size_t)NTOK*DIM_];
__device__ float g_v[(size_t)NTOK*DIM_];
__device__ float g_attn[B_*HEADS_*32*32];
__device__ float g_attn_sm[B_*HEADS_*32*32];
__device__ float g_ssq[B_*HEADS_*32];
__device__ float g_ssk[B_*HEADS_*32];
__device__ float g_M[B_*DIM_*DIM_];

// ---------------- tf32 helpers ----------------------------------------------
__device__ __forceinline__ uint32_t f2tf(float f) {
    uint32_t u; asm("cvt.rna.tf32.f32 %0, %1;" : "=r"(u) : "f"(f)); return u;
}
__device__ __forceinline__ void mma8(float* c,
                                     uint32_t a0, uint32_t a1, uint32_t a2, uint32_t a3,
                                     uint32_t b0, uint32_t b1) {
    asm volatile(
        "mma.sync.aligned.m16n8k8.row.col.f32.tf32.tf32.f32 "
        "{%0,%1,%2,%3},{%4,%5,%6,%7},{%8,%9},{%0,%1,%2,%3};"
        : "+f"(c[0]), "+f"(c[1]), "+f"(c[2]), "+f"(c[3])
        : "r"(a0), "r"(a1), "r"(a2), "r"(a3), "r"(b0), "r"(b1));
}

// ---------------- zero accumulators (graph-replay safe) ---------------------
__global__ void zero_kernel() {
    int i = blockIdx.x*blockDim.x + threadIdx.x;
    if (i < B_*HEADS_*32*32) g_attn[i] = 0.f;
    if (i < B_*HEADS_*32) { g_ssq[i] = 0.f; g_ssk[i] = 0.f; }
}

// =============================================================================
// GEMM: A resident [128k][perm(128 tok)] (stride 132), B chunk [16k][perm(col)]
// perm(c) = (c&7)*16 + (c>>3)  (dense 0..127)
// =============================================================================
#define LDAW 132
#define AS_WORDS (128*LDAW)
#define BS_WORDS (16*LDAW)
#define GEMM_SMEM ((AS_WORDS + BS_WORDS)*4)

__device__ __forceinline__ void gemm_pass(const uint32_t* __restrict__ As,
                                          uint32_t* __restrict__ Bs,
                                          const float* __restrict__ W,
                                          float* __restrict__ Out,
                                          const float* __restrict__ bias,
                                          bool rmw)
{
    int tid = threadIdx.x;
    int lane = tid & 31, warp = tid >> 5;
    int wm = (warp & 3) * 32, wn = (warp >> 2) * 64;
    int g  = lane >> 2;
    int kq = lane & 3;
    float acc[2][8][4];
#pragma unroll
    for (int mt = 0; mt < 2; mt++)
#pragma unroll
        for (int nt = 0; nt < 8; nt++)
#pragma unroll
            for (int r = 0; r < 4; r++) acc[mt][nt][r] = 0.f;

    int kk = tid >> 4;           // 0..15 : B-chunk row
    int n0 = (tid & 15) << 3;    // col base
    int bb = kk*LDAW + (tid & 15);
    float4 w0 = *(const float4*)(W + kk*128 + n0);
    float4 w1 = *(const float4*)(W + kk*128 + n0 + 4);

    for (int k0 = 0; k0 < 8; k0++) {
        // store chunk (permuted: col n0+j -> j*16 + (n0>>3))
        Bs[bb+  0]=f2tf(w0.x); Bs[bb+ 16]=f2tf(w0.y); Bs[bb+ 32]=f2tf(w0.z); Bs[bb+ 48]=f2tf(w0.w);
        Bs[bb+ 64]=f2tf(w1.x); Bs[bb+ 80]=f2tf(w1.y); Bs[bb+ 96]=f2tf(w1.z); Bs[bb+112]=f2tf(w1.w);
        __syncthreads();
        if (k0 < 7) {
            w0 = *(const float4*)(W + (k0+1)*2048 + kk*128 + n0);
            w1 = *(const float4*)(W + (k0+1)*2048 + kk*128 + n0 + 4);
        }
#pragma unroll
        for (int ks = 0; ks < 2; ks++) {
            int arow = k0*16 + ks*8 + kq;
            int brow = ks*8 + kq;
            uint4 A0 = *(const uint4*)&As[arow*LDAW     + g*16 + (wm>>3)];
            uint4 A4 = *(const uint4*)&As[(arow+4)*LDAW + g*16 + (wm>>3)];
            uint4 B0 = *(const uint4*)&Bs[brow*LDAW     + g*16 + (wn>>3)];
            uint4 B0h= *(const uint4*)&Bs[brow*LDAW     + g*16 + (wn>>3) + 4];
            uint4 B4 = *(const uint4*)&Bs[(brow+4)*LDAW + g*16 + (wn>>3)];
            uint4 B4h= *(const uint4*)&Bs[(brow+4)*LDAW + g*16 + (wn>>3) + 4];
            uint32_t a0[4] = {A0.x, A0.y, A4.x, A4.y};
            uint32_t a1[4] = {A0.z, A0.w, A4.z, A4.w};
            uint32_t b0a[8] = {B0.x,B0.y,B0.z,B0.w,B0h.x,B0h.y,B0h.z,B0h.w};
            uint32_t b1a[8] = {B4.x,B4.y,B4.z,B4.w,B4h.x,B4h.y,B4h.z,B4h.w};
#pragma unroll
            for (int nt = 0; nt < 8; nt++) {
                mma8(acc[0][nt], a0[0],a0[1],a0[2],a0[3], b0a[nt], b1a[nt]);
                mma8(acc[1][nt], a1[0],a1[1],a1[2],a1[3], b0a[nt], b1a[nt]);
            }
        }
        __syncthreads();
    }
    // epilogue
    int row0 = wm + g;
    int col0 = wn + kq*2;
#pragma unroll
    for (int mt = 0; mt < 2; mt++) {
#pragma unroll
        for (int nt = 0; nt < 8; nt++) {
            int r = row0 + mt*16;
            int c = col0 + nt*8;
            float b0v = bias ? bias[c]   : 0.f;
            float b1v = bias ? bias[c+1] : 0.f;
            if (rmw) {
                float2 o0 = *(float2*)(Out + (size_t)r*128 + c);
                float2 o1 = *(float2*)(Out + (size_t)(r+8)*128 + c);
                o0.x += acc[mt][nt][0] + b0v; o0.y += acc[mt][nt][1] + b1v;
                o1.x += acc[mt][nt][2] + b0v; o1.y += acc[mt][nt][3] + b1v;
                *(float2*)(Out + (size_t)r*128 + c)     = o0;
                *(float2*)(Out + (size_t)(r+8)*128 + c) = o1;
            } else {
                float2 v0 = make_float2(acc[mt][nt][0] + b0v, acc[mt][nt][1] + b1v);
                float2 v1 = make_float2(acc[mt][nt][2] + b0v, acc[mt][nt][3] + b1v);
                *(float2*)(Out + (size_t)r*128 + c)     = v0;
                *(float2*)(Out + (size_t)(r+8)*128 + c) = v1;
            }
        }
    }
}

__device__ __forceinline__ void stage_A(uint32_t* __restrict__ As,
                                        const float* __restrict__ X)
{
    int tid = threadIdx.x;
    int t  = tid >> 1;
    int kh = (tid & 1) * 64;
    int pt = ((t & 7) << 4) + (t >> 3);
#pragma unroll 4
    for (int i = 0; i < 64; i += 4) {
        float4 v = *(const float4*)(X + (size_t)t*128 + kh + i);
        As[(kh+i+0)*LDAW + pt] = f2tf(v.x);
        As[(kh+i+1)*LDAW + pt] = f2tf(v.y);
        As[(kh+i+2)*LDAW + pt] = f2tf(v.z);
        As[(kh+i+3)*LDAW + pt] = f2tf(v.w);
    }
    __syncthreads();
}

__global__ void __launch_bounds__(256) qkv_kernel(const float* __restrict__ x,
                                                  const float* __restrict__ Wq,
                                                  const float* __restrict__ Wk,
                                                  const float* __restrict__ Wv)
{
    extern __shared__ uint32_t smu[];
    uint32_t* As = smu;
    uint32_t* Bs = smu + AS_WORDS;
    size_t tok0 = (size_t)blockIdx.x * 128;
    stage_A(As, x + tok0*128);
    gemm_pass(As, Bs, Wq, g_q + tok0*128, nullptr, false);
    gemm_pass(As, Bs, Wk, g_k + tok0*128, nullptr, false);
    gemm_pass(As, Bs, Wv, g_v + tok0*128, nullptr, false);
}

__global__ void __launch_bounds__(256) vm_kernel(const float* __restrict__ bproj,
                                                 float* __restrict__ out)
{
    extern __shared__ uint32_t smu[];
    uint32_t* As = smu;
    uint32_t* Bs = smu + AS_WORDS;
    size_t tok0 = (size_t)blockIdx.x * 128;
    int b = blockIdx.x >> 9;
    stage_A(As, g_v + tok0*128);
    gemm_pass(As, Bs, g_M + (size_t)b*DIM_*DIM_, out + tok0*128, bproj, true);
}

// ---------------- attn accumulation via tf32 mma ----------------------------
#define NCHUNK 16
#define LQS 36
__global__ void __launch_bounds__(256) attn_kernel()
{
    __shared__ uint32_t qs[64*LQS];
    __shared__ uint32_t ks[64*LQS];
    int b = blockIdx.z, h = blockIdx.y;
    int n0 = blockIdx.x * (HW_ / NCHUNK);
    int tid = threadIdx.x;
    int lane = tid & 31, warp = tid >> 5;
    float acc[2][4][4];
#pragma unroll
    for (int mt = 0; mt < 2; mt++)
#pragma unroll
        for (int nt = 0; nt < 4; nt++)
#pragma unroll
            for (int r = 0; r < 4; r++) acc[mt][nt][r] = 0.f;
    float ssk_acc = 0.f, ssq_acc = 0.f;

    for (int sub = 0; sub < (HW_/NCHUNK)/64; sub++) {
        int t0 = n0 + sub*64;
        {
            int r  = tid >> 2;
            int c8 = (tid & 3) << 3;
            size_t base = ((size_t)(b*HW_ + t0 + r))*128 + h*32 + c8;
            float4 a0 = *(const float4*)(g_q + base);
            float4 a1 = *(const float4*)(g_q + base + 4);
            qs[r*LQS+c8+0]=f2tf(a0.x); qs[r*LQS+c8+1]=f2tf(a0.y);
            qs[r*LQS+c8+2]=f2tf(a0.z); qs[r*LQS+c8+3]=f2tf(a0.w);
            qs[r*LQS+c8+4]=f2tf(a1.x); qs[r*LQS+c8+5]=f2tf(a1.y);
            qs[r*LQS+c8+6]=f2tf(a1.z); qs[r*LQS+c8+7]=f2tf(a1.w);
            float4 b0 = *(const float4*)(g_k + base);
            float4 b1 = *(const float4*)(g_k + base + 4);
            ks[r*LQS+c8+0]=f2tf(b0.x); ks[r*LQS+c8+1]=f2tf(b0.y);
            ks[r*LQS+c8+2]=f2tf(b0.z); ks[r*LQS+c8+3]=f2tf(b0.w);
            ks[r*LQS+c8+4]=f2tf(b1.x); ks[r*LQS+c8+5]=f2tf(b1.y);
            ks[r*LQS+c8+6]=f2tf(b1.z); ks[r*LQS+c8+7]=f2tf(b1.w);
        }
        __syncthreads();
        int kt = warp * 8;
        int ar = kt + (lane & 3);
        int dq = lane >> 2;
        uint32_t a[2][4];
#pragma unroll
        for (int mt = 0; mt < 2; mt++) {
            int d = dq + mt*16;
            a[mt][0] = ks[ar*LQS + d];
            a[mt][1] = ks[ar*LQS + d + 8];
            a[mt][2] = ks[(ar+4)*LQS + d];
            a[mt][3] = ks[(ar+4)*LQS + d + 8];
        }
#pragma unroll
        for (int nt = 0; nt < 4; nt++) {
            int e = dq + nt*8;
            uint32_t b0 = qs[ar*LQS + e];
            uint32_t b1 = qs[(ar+4)*LQS + e];
#pragma unroll
            for (int mt = 0; mt < 2; mt++)
                mma8(acc[mt][nt], a[mt][0], a[mt][1], a[mt][2], a[mt][3], b0, b1);
        }
#pragma unroll
        for (int tt = 0; tt < 8; tt++) {
            float kv = __uint_as_float(ks[(kt+tt)*LQS + lane]);
            float qv = __uint_as_float(qs[(kt+tt)*LQS + lane]);
            ssk_acc += kv*kv;
            ssq_acc += qv*qv;
        }
        __syncthreads();
    }
    int bh = b*HEADS_ + h;
    int dq = lane >> 2;
    int e0 = (lane & 3)*2;
#pragma unroll
    for (int mt = 0; mt < 2; mt++) {
#pragma unroll
        for (int nt = 0; nt < 4; nt++) {
            int d = dq + mt*16;
            int e = e0 + nt*8;
            atomicAdd(&g_attn[(bh*32 + d)*32 + e],       acc[mt][nt][0]);
            atomicAdd(&g_attn[(bh*32 + d)*32 + e + 1],   acc[mt][nt][1]);
            atomicAdd(&g_attn[(bh*32 + d+8)*32 + e],     acc[mt][nt][2]);
            atomicAdd(&g_attn[(bh*32 + d+8)*32 + e + 1], acc[mt][nt][3]);
        }
    }
    atomicAdd(&g_ssk[bh*32 + lane], ssk_acc);
    atomicAdd(&g_ssq[bh*32 + lane], ssq_acc);
}

// ---------------- scale + softmax over e ------------------------------------
__global__ void __launch_bounds__(1024) softmax_kernel(const float* __restrict__ rescale)
{
    int bh = blockIdx.x;
    int h = bh & 3;
    int tid = threadIdx.x;
    int d = tid >> 5, e = tid & 31;
    float nk = fmaxf(sqrtf(g_ssk[bh*32 + d]), 1e-12f);
    float nq = fmaxf(sqrtf(g_ssq[bh*32 + e]), 1e-12f);
    float val = g_attn[bh*1024 + d*32 + e] * rescale[h] / (nk*nq);
    float m = val;
#pragma unroll
    for (int off = 16; off > 0; off >>= 1) m = fmaxf(m, __shfl_xor_sync(0xffffffffu, m, off));
    float ex = expf(val - m);
    float s = ex;
#pragma unroll
    for (int off = 16; off > 0; off >>= 1) s += __shfl_xor_sync(0xffffffffu, s, off);
    g_attn_sm[bh*1024 + d*32 + e] = ex / s;
}

// ---------------- M[b] = blockdiag(softmax attn) @ Wproj --------------------
__global__ void __launch_bounds__(256) m_kernel(const float* __restrict__ Wproj)
{
    __shared__ float as[32*33];
    __shared__ float wp[32*128];
    int bh = blockIdx.x;
    int b = bh >> 2, h = bh & 3;
    int tid = threadIdx.x;
    for (int i = tid; i < 1024; i += 256) {
        int d = i >> 5, e = i & 31;
        as[d*33 + e] = g_attn_sm[bh*1024 + i];
    }
    for (int i = tid; i < 1024; i += 256)
        ((float4*)wp)[i] = ((const float4*)(Wproj + (size_t)h*32*128))[i];
    __syncthreads();
    int c  = tid & 127;
    int eg = tid >> 7;
    for (int ee = 0; ee < 16; ee++) {
        int e = eg*16 + ee;
        float a = 0.f;
#pragma unroll
        for (int d = 0; d < 32; d++) a += as[d*33 + e] * wp[d*128 + c];
        g_M[(size_t)b*16384 + (h*32 + e)*128 + c] = a;
    }
}

// ---------------- fused Gabor (separable) + GELU + pointwise (tf32 mma) -----
// words: vt 6272 | ts 3696 | gs_t 32*132=4224 | pws_t 32*132=4224
#define GB_VT 6272
#define GB_TS 3696
#define LDGT 132
#define GB_TOTW (GB_VT + GB_TS + 32*LDGT + 32*LDGT)

__global__ void __launch_bounds__(256) gabor_kernel(const float* __restrict__ dw_w,
                                                    const float* __restrict__ dw_b,
                                                    const float* __restrict__ pw_w,
                                                    const float* __restrict__ pw_b,
                                                    float* __restrict__ out)
{
    extern __shared__ float smf[];
    float* vt = smf;
    float* ts = smf + GB_VT;
    uint32_t* gs_t  = (uint32_t*)(smf + GB_VT + GB_TS);
    uint32_t* pws_t = gs_t + 32*LDGT;

    int b  = blockIdx.z;
    int y0 = blockIdx.y << 3;
    int x0 = blockIdx.x << 3;
    int tid = threadIdx.x;
    int lane = tid & 31, warp = tid >> 5;
    int pq = lane >> 2;
    int kq = lane & 3;
    int wn = warp * 16;

    float acc[4][2][4];
#pragma unroll
    for (int mt = 0; mt < 4; mt++)
#pragma unroll
        for (int nt = 0; nt < 2; nt++)
#pragma unroll
            for (int r = 0; r < 4; r++) acc[mt][nt][r] = 0.f;

    for (int cg = 0; cg < 4; cg++) {
        int c0 = cg << 5;
        __syncthreads();
        {   // load v halo tile [14][14][32]
            int c = tid & 31;
            for (int p = tid >> 5; p < 196; p += 8) {
                int row = p / 14, col = p % 14;
                int gy = y0 - 3 + row, gx = x0 - 3 + col;
                float val = 0.f;
                if ((unsigned)gy < 256u && (unsigned)gx < 256u)
                    val = g_v[((size_t)(b*HW_ + gy*256 + gx))*128 + c0 + c];
                vt[(row*14 + col)*32 + c] = val;
            }
        }
        for (int s = 0; s < 4; s++) {
            __syncthreads();
            {   // horizontal pass
                float Bf[7];
#pragma unroll
                for (int j = 0; j < 7; j++) Bf[j] = dw_w[s*49 + 28 + j];
                int c = tid & 31;
                for (int rx = tid >> 5; rx < 112; rx += 8) {
                    int row = rx >> 3, xx = rx & 7;
                    float sum = 0.f;
#pragma unroll
                    for (int j = 0; j < 7; j++) sum += Bf[j]*vt[(row*14 + xx + j)*32 + c];
                    ts[rx*33 + c] = sum;
                }
            }
            {   // stage pointwise weights k-major permuted: pws_t[cc][perm(o)]
                int o = tid >> 1, cc0 = (tid & 1) << 4;
                int po = ((o & 7) << 4) + (o >> 3);
#pragma unroll 4
                for (int q = 0; q < 16; q++) {
                    int cc = cc0 + q;
                    pws_t[cc*LDGT + po] = f2tf(pw_w[(size_t)o*512 + (c0+cc)*4 + s]);
                }
            }
            __syncthreads();
            {   // vertical pass + bias + exact GELU -> gs_t[cc][perm(pix)]
                float Af[7];
#pragma unroll
                for (int i = 0; i < 7; i++) Af[i] = dw_w[s*49 + i*7 + 4];
                int c = tid & 31;
                int rbase = tid >> 5;   // xx
                float bias = dw_b[(c0+c)*4 + s];
                uint32_t gres[8];
#pragma unroll
                for (int i = 0; i < 8; i++) {   // y = i, xx = rbase
                    float sum = bias;
#pragma unroll
                    for (int t7 = 0; t7 < 7; t7++)
                        sum += Af[t7]*ts[((i+t7)*8 + rbase)*33 + c];
                    float g = 0.5f*sum*(1.f + erff(sum*0.70710678118654752f));
                    gres[i] = f2tf(g);
                }
                *(uint4*)&gs_t[c*LDGT + rbase*16]     = make_uint4(gres[0],gres[1],gres[2],gres[3]);
                *(uint4*)&gs_t[c*LDGT + rbase*16 + 4] = make_uint4(gres[4],gres[5],gres[6],gres[7]);
            }
            __syncthreads();
            // pointwise via mma: C[64 pix][128 out] += g[64][32k] * pw
#pragma unroll
            for (int ks = 0; ks < 32; ks += 8) {
                int ar = ks + kq;
                uint4 G0 = *(const uint4*)&gs_t[ar*LDGT     + pq*16];
                uint4 G1 = *(const uint4*)&gs_t[ar*LDGT     + pq*16 + 4];
                uint4 G4 = *(const uint4*)&gs_t[(ar+4)*LDGT + pq*16];
                uint4 G5 = *(const uint4*)&gs_t[(ar+4)*LDGT + pq*16 + 4];
                uint2 P0 = *(const uint2*)&pws_t[ar*LDGT     + pq*16 + 2*warp];
                uint2 P4 = *(const uint2*)&pws_t[(ar+4)*LDGT + pq*16 + 2*warp];
                uint32_t a[4][4] = {
                    {G0.x, G0.y, G4.x, G4.y},
                    {G0.z, G0.w, G4.z, G4.w},
                    {G1.x, G1.y, G5.x, G5.y},
                    {G1.z, G1.w, G5.z, G5.w}};
#pragma unroll
                for (int mt = 0; mt < 4; mt++) {
                    mma8(acc[mt][0], a[mt][0],a[mt][1],a[mt][2],a[mt][3], P0.x, P4.x);
                    mma8(acc[mt][1], a[mt][0],a[mt][1],a[mt][2],a[mt][3], P0.y, P4.y);
                }
            }
        }
    }
    // epilogue: WRITE out (first writer) = out_p + pw_b
#pragma unroll
    for (int mt = 0; mt < 4; mt++) {
#pragma unroll
        for (int nt = 0; nt < 2; nt++) {
            int c = wn + nt*8 + kq*2;
            float pb0 = pw_b[c], pb1 = pw_b[c+1];
#pragma unroll
            for (int half = 0; half < 2; half++) {
                int pix = mt*16 + pq + half*8;
                int y = pix >> 3, xx = pix & 7;
                size_t base = ((size_t)(b*HW_ + (y0+y)*256 + x0+xx))*128 + c;
                float2 o0;
                o0.x = acc[mt][nt][half*2+0] + pb0;
                o0.y = acc[mt][nt][half*2+1] + pb1;
                *(float2*)(out + base) = o0;
            }
        }
    }
}

// ---------------------------------------------------------------------------
extern "C" void kernel_launch(void* const* d_in, const int* in_sizes, int n_in,
                              void* d_out, int out_size)
{
    const float* x       = (const float*)d_in[0];
    const float* Wq      = (const float*)d_in[1];
    const float* Wk      = (const float*)d_in[2];
    const float* Wv      = (const float*)d_in[3];
    const float* rescale = (const float*)d_in[4];
    const float* Wproj   = (const float*)d_in[5];
    const float* bproj   = (const float*)d_in[6];
    const float* dw_w    = (const float*)d_in[7];
    const float* dw_b    = (const float*)d_in[8];
    const float* pw_w    = (const float*)d_in[9];
    const float* pw_b    = (const float*)d_in[10];
    float* out = (float*)d_out;

    cudaFuncSetAttribute(qkv_kernel, cudaFuncAttributeMaxDynamicSharedMemorySize, GEMM_SMEM);
    cudaFuncSetAttribute(vm_kernel,  cudaFuncAttributeMaxDynamicSharedMemorySize, GEMM_SMEM);
    cudaFuncSetAttribute(gabor_kernel, cudaFuncAttributeMaxDynamicSharedMemorySize,
                         GB_TOTW * (int)sizeof(float));

    zero_kernel<<<64, 256>>>();
    qkv_kernel<<<NTOK/128, 256, GEMM_SMEM>>>(x, Wq, Wk, Wv);
    attn_kernel<<<dim3(NCHUNK, HEADS_, B_), 256>>>();
    gabor_kernel<<<dim3(32, 32, B_), 256, GB_TOTW * sizeof(float)>>>(
        dw_w, dw_b, pw_w, pw_b, out);
    softmax_kernel<<<B_*HEADS_, 1024>>>(rescale);
    m_kernel<<<B_*HEADS_, 256>>>(Wproj);
    vm_kernel<<<NTOK/128, 256, GEMM_SMEM>>>(bproj, out);
}

// round 5
// speedup vs baseline: 1.4970x; 1.0005x over previous
#include <cuda_runtime.h>
#include <math.h>
#include <stdint.h>

#define B_ 4
#define HW_ 65536
#define NTOK (B_*HW_)      // 262144 tokens
#define DIM_ 128
#define HEADS_ 4

// ---------------- scratch (device globals; no allocations allowed) ----------
__device__ float g_q[(size_t)NTOK*DIM_];
__device__ float g_k[(size_t)NTOK*DIM_];
__device__ float g_v[(size_t)NTOK*DIM_];
__device__ float g_attn[B_*HEADS_*32*32];
__device__ float g_attn_sm[B_*HEADS_*32*32];
__device__ float g_ssq[B_*HEADS_*32];
__device__ float g_ssk[B_*HEADS_*32];
__device__ float g_M[B_*DIM_*DIM_];

// ---------------- tf32 helpers ----------------------------------------------
__device__ __forceinline__ uint32_t f2tf(float f) {
    uint32_t u; asm("cvt.rna.tf32.f32 %0, %1;" : "=r"(u) : "f"(f)); return u;
}
__device__ __forceinline__ void mma8(float* c,
                                     uint32_t a0, uint32_t a1, uint32_t a2, uint32_t a3,
                                     uint32_t b0, uint32_t b1) {
    asm volatile(
        "mma.sync.aligned.m16n8k8.row.col.f32.tf32.tf32.f32 "
        "{%0,%1,%2,%3},{%4,%5,%6,%7},{%8,%9},{%0,%1,%2,%3};"
        : "+f"(c[0]), "+f"(c[1]), "+f"(c[2]), "+f"(c[3])
        : "r"(a0), "r"(a1), "r"(a2), "r"(a3), "r"(b0), "r"(b1));
}

// ---------------- zero accumulators (graph-replay safe) ---------------------
__global__ void zero_kernel() {
    int i = blockIdx.x*blockDim.x + threadIdx.x;
    if (i < B_*HEADS_*32*32) g_attn[i] = 0.f;
    if (i < B_*HEADS_*32) { g_ssq[i] = 0.f; g_ssk[i] = 0.f; }
}

// =============================================================================
// GEMM: A resident [128k][perm(128 tok)] (stride 132), B chunk [16k][perm(col)]
// perm(c) = (c&7)*16 + (c>>3)  (dense 0..127)
// =============================================================================
#define LDAW 132
#define AS_WORDS (128*LDAW)
#define BS_WORDS (16*LDAW)
#define GEMM_SMEM ((AS_WORDS + BS_WORDS)*4)

__device__ __forceinline__ void gemm_pass(const uint32_t* __restrict__ As,
                                          uint32_t* __restrict__ Bs,
                                          const float* __restrict__ W,
                                          float* __restrict__ Out,
                                          const float* __restrict__ bias,
                                          bool rmw)
{
    int tid = threadIdx.x;
    int lane = tid & 31, warp = tid >> 5;
    int wm = (warp & 3) * 32, wn = (warp >> 2) * 64;
    int g  = lane >> 2;
    int kq = lane & 3;
    float acc[2][8][4];
#pragma unroll
    for (int mt = 0; mt < 2; mt++)
#pragma unroll
        for (int nt = 0; nt < 8; nt++)
#pragma unroll
            for (int r = 0; r < 4; r++) acc[mt][nt][r] = 0.f;

    int kk = tid >> 4;           // 0..15 : B-chunk row
    int n0 = (tid & 15) << 3;    // col base
    int bb = kk*LDAW + (tid & 15);
    float4 w0 = *(const float4*)(W + kk*128 + n0);
    float4 w1 = *(const float4*)(W + kk*128 + n0 + 4);

    for (int k0 = 0; k0 < 8; k0++) {
        // store chunk (permuted: col n0+j -> j*16 + (n0>>3))
        Bs[bb+  0]=f2tf(w0.x); Bs[bb+ 16]=f2tf(w0.y); Bs[bb+ 32]=f2tf(w0.z); Bs[bb+ 48]=f2tf(w0.w);
        Bs[bb+ 64]=f2tf(w1.x); Bs[bb+ 80]=f2tf(w1.y); Bs[bb+ 96]=f2tf(w1.z); Bs[bb+112]=f2tf(w1.w);
        __syncthreads();
        if (k0 < 7) {
            w0 = *(const float4*)(W + (k0+1)*2048 + kk*128 + n0);
            w1 = *(const float4*)(W + (k0+1)*2048 + kk*128 + n0 + 4);
        }
#pragma unroll
        for (int ks = 0; ks < 2; ks++) {
            int arow = k0*16 + ks*8 + kq;
            int brow = ks*8 + kq;
            uint4 A0 = *(const uint4*)&As[arow*LDAW     + g*16 + (wm>>3)];
            uint4 A4 = *(const uint4*)&As[(arow+4)*LDAW + g*16 + (wm>>3)];
            uint4 B0 = *(const uint4*)&Bs[brow*LDAW     + g*16 + (wn>>3)];
            uint4 B0h= *(const uint4*)&Bs[brow*LDAW     + g*16 + (wn>>3) + 4];
            uint4 B4 = *(const uint4*)&Bs[(brow+4)*LDAW + g*16 + (wn>>3)];
            uint4 B4h= *(const uint4*)&Bs[(brow+4)*LDAW + g*16 + (wn>>3) + 4];
            uint32_t a0[4] = {A0.x, A0.y, A4.x, A4.y};
            uint32_t a1[4] = {A0.z, A0.w, A4.z, A4.w};
            uint32_t b0a[8] = {B0.x,B0.y,B0.z,B0.w,B0h.x,B0h.y,B0h.z,B0h.w};
            uint32_t b1a[8] = {B4.x,B4.y,B4.z,B4.w,B4h.x,B4h.y,B4h.z,B4h.w};
#pragma unroll
            for (int nt = 0; nt < 8; nt++) {
                mma8(acc[0][nt], a0[0],a0[1],a0[2],a0[3], b0a[nt], b1a[nt]);
                mma8(acc[1][nt], a1[0],a1[1],a1[2],a1[3], b0a[nt], b1a[nt]);
            }
        }
        __syncthreads();
    }
    // epilogue
    int row0 = wm + g;
    int col0 = wn + kq*2;
#pragma unroll
    for (int mt = 0; mt < 2; mt++) {
#pragma unroll
        for (int nt = 0; nt < 8; nt++) {
            int r = row0 + mt*16;
            int c = col0 + nt*8;
            float b0v = bias ? bias[c]   : 0.f;
            float b1v = bias ? bias[c+1] : 0.f;
            if (rmw) {
                float2 o0 = *(float2*)(Out + (size_t)r*128 + c);
                float2 o1 = *(float2*)(Out + (size_t)(r+8)*128 + c);
                o0.x += acc[mt][nt][0] + b0v; o0.y += acc[mt][nt][1] + b1v;
                o1.x += acc[mt][nt][2] + b0v; o1.y += acc[mt][nt][3] + b1v;
                *(float2*)(Out + (size_t)r*128 + c)     = o0;
                *(float2*)(Out + (size_t)(r+8)*128 + c) = o1;
            } else {
                float2 v0 = make_float2(acc[mt][nt][0] + b0v, acc[mt][nt][1] + b1v);
                float2 v1 = make_float2(acc[mt][nt][2] + b0v, acc[mt][nt][3] + b1v);
                *(float2*)(Out + (size_t)r*128 + c)     = v0;
                *(float2*)(Out + (size_t)(r+8)*128 + c) = v1;
            }
        }
    }
}

__device__ __forceinline__ void stage_A(uint32_t* __restrict__ As,
                                        const float* __restrict__ X)
{
    int tid = threadIdx.x;
    int t  = tid >> 1;
    int kh = (tid & 1) * 64;
    int pt = ((t & 7) << 4) + (t >> 3);
#pragma unroll 4
    for (int i = 0; i < 64; i += 4) {
        float4 v = *(const float4*)(X + (size_t)t*128 + kh + i);
        As[(kh+i+0)*LDAW + pt] = f2tf(v.x);
        As[(kh+i+1)*LDAW + pt] = f2tf(v.y);
        As[(kh+i+2)*LDAW + pt] = f2tf(v.z);
        As[(kh+i+3)*LDAW + pt] = f2tf(v.w);
    }
    __syncthreads();
}

__global__ void __launch_bounds__(256) qkv_kernel(const float* __restrict__ x,
                                                  const float* __restrict__ Wq,
                                                  const float* __restrict__ Wk,
                                                  const float* __restrict__ Wv)
{
    extern __shared__ uint32_t smu[];
    uint32_t* As = smu;
    uint32_t* Bs = smu + AS_WORDS;
    size_t tok0 = (size_t)blockIdx.x * 128;
    stage_A(As, x + tok0*128);
    gemm_pass(As, Bs, Wq, g_q + tok0*128, nullptr, false);
    gemm_pass(As, Bs, Wk, g_k + tok0*128, nullptr, false);
    gemm_pass(As, Bs, Wv, g_v + tok0*128, nullptr, false);
}

__global__ void __launch_bounds__(256) vm_kernel(const float* __restrict__ bproj,
                                                 float* __restrict__ out)
{
    extern __shared__ uint32_t smu[];
    uint32_t* As = smu;
    uint32_t* Bs = smu + AS_WORDS;
    size_t tok0 = (size_t)blockIdx.x * 128;
    int b = blockIdx.x >> 9;
    stage_A(As, g_v + tok0*128);
    gemm_pass(As, Bs, g_M + (size_t)b*DIM_*DIM_, out + tok0*128, bproj, true);
}

// ---------------- attn accumulation via tf32 mma ----------------------------
#define NCHUNK 16
#define LQS 36
__global__ void __launch_bounds__(256) attn_kernel()
{
    __shared__ uint32_t qs[64*LQS];
    __shared__ uint32_t ks[64*LQS];
    int b = blockIdx.z, h = blockIdx.y;
    int n0 = blockIdx.x * (HW_ / NCHUNK);
    int tid = threadIdx.x;
    int lane = tid & 31, warp = tid >> 5;
    float acc[2][4][4];
#pragma unroll
    for (int mt = 0; mt < 2; mt++)
#pragma unroll
        for (int nt = 0; nt < 4; nt++)
#pragma unroll
            for (int r = 0; r < 4; r++) acc[mt][nt][r] = 0.f;
    float ssk_acc = 0.f, ssq_acc = 0.f;

    for (int sub = 0; sub < (HW_/NCHUNK)/64; sub++) {
        int t0 = n0 + sub*64;
        {
            int r  = tid >> 2;
            int c8 = (tid & 3) << 3;
            size_t base = ((size_t)(b*HW_ + t0 + r))*128 + h*32 + c8;
            float4 a0 = *(const float4*)(g_q + base);
            float4 a1 = *(const float4*)(g_q + base + 4);
            qs[r*LQS+c8+0]=f2tf(a0.x); qs[r*LQS+c8+1]=f2tf(a0.y);
            qs[r*LQS+c8+2]=f2tf(a0.z); qs[r*LQS+c8+3]=f2tf(a0.w);
            qs[r*LQS+c8+4]=f2tf(a1.x); qs[r*LQS+c8+5]=f2tf(a1.y);
            qs[r*LQS+c8+6]=f2tf(a1.z); qs[r*LQS+c8+7]=f2tf(a1.w);
            float4 b0 = *(const float4*)(g_k + base);
            float4 b1 = *(const float4*)(g_k + base + 4);
            ks[r*LQS+c8+0]=f2tf(b0.x); ks[r*LQS+c8+1]=f2tf(b0.y);
            ks[r*LQS+c8+2]=f2tf(b0.z); ks[r*LQS+c8+3]=f2tf(b0.w);
            ks[r*LQS+c8+4]=f2tf(b1.x); ks[r*LQS+c8+5]=f2tf(b1.y);
            ks[r*LQS+c8+6]=f2tf(b1.z); ks[r*LQS+c8+7]=f2tf(b1.w);
        }
        __syncthreads();
        int kt = warp * 8;
        int ar = kt + (lane & 3);
        int dq = lane >> 2;
        uint32_t a[2][4];
#pragma unroll
        for (int mt = 0; mt < 2; mt++) {
            int d = dq + mt*16;
            a[mt][0] = ks[ar*LQS + d];
            a[mt][1] = ks[ar*LQS + d + 8];
            a[mt][2] = ks[(ar+4)*LQS + d];
            a[mt][3] = ks[(ar+4)*LQS + d + 8];
        }
#pragma unroll
        for (int nt = 0; nt < 4; nt++) {
            int e = dq + nt*8;
            uint32_t b0 = qs[ar*LQS + e];
            uint32_t b1 = qs[(ar+4)*LQS + e];
#pragma unroll
            for (int mt = 0; mt < 2; mt++)
                mma8(acc[mt][nt], a[mt][0], a[mt][1], a[mt][2], a[mt][3], b0, b1);
        }
#pragma unroll
        for (int tt = 0; tt < 8; tt++) {
            float kv = __uint_as_float(ks[(kt+tt)*LQS + lane]);
            float qv = __uint_as_float(qs[(kt+tt)*LQS + lane]);
            ssk_acc += kv*kv;
            ssq_acc += qv*qv;
        }
        __syncthreads();
    }
    int bh = b*HEADS_ + h;
    int dq = lane >> 2;
    int e0 = (lane & 3)*2;
#pragma unroll
    for (int mt = 0; mt < 2; mt++) {
#pragma unroll
        for (int nt = 0; nt < 4; nt++) {
            int d = dq + mt*16;
            int e = e0 + nt*8;
            atomicAdd(&g_attn[(bh*32 + d)*32 + e],       acc[mt][nt][0]);
            atomicAdd(&g_attn[(bh*32 + d)*32 + e + 1],   acc[mt][nt][1]);
            atomicAdd(&g_attn[(bh*32 + d+8)*32 + e],     acc[mt][nt][2]);
            atomicAdd(&g_attn[(bh*32 + d+8)*32 + e + 1], acc[mt][nt][3]);
        }
    }
    atomicAdd(&g_ssk[bh*32 + lane], ssk_acc);
    atomicAdd(&g_ssq[bh*32 + lane], ssq_acc);
}

// ---------------- scale + softmax over e ------------------------------------
__global__ void __launch_bounds__(1024) softmax_kernel(const float* __restrict__ rescale)
{
    int bh = blockIdx.x;
    int h = bh & 3;
    int tid = threadIdx.x;
    int d = tid >> 5, e = tid & 31;
    float nk = fmaxf(sqrtf(g_ssk[bh*32 + d]), 1e-12f);
    float nq = fmaxf(sqrtf(g_ssq[bh*32 + e]), 1e-12f);
    float val = g_attn[bh*1024 + d*32 + e] * rescale[h] / (nk*nq);
    float m = val;
#pragma unroll
    for (int off = 16; off > 0; off >>= 1) m = fmaxf(m, __shfl_xor_sync(0xffffffffu, m, off));
    float ex = expf(val - m);
    float s = ex;
#pragma unroll
    for (int off = 16; off > 0; off >>= 1) s += __shfl_xor_sync(0xffffffffu, s, off);
    g_attn_sm[bh*1024 + d*32 + e] = ex / s;
}

// ---------------- M[b] = blockdiag(softmax attn) @ Wproj --------------------
__global__ void __launch_bounds__(256) m_kernel(const float* __restrict__ Wproj)
{
    __shared__ float as[32*33];
    __shared__ float wp[32*128];
    int bh = blockIdx.x;
    int b = bh >> 2, h = bh & 3;
    int tid = threadIdx.x;
    for (int i = tid; i < 1024; i += 256) {
        int d = i >> 5, e = i & 31;
        as[d*33 + e] = g_attn_sm[bh*1024 + i];
    }
    for (int i = tid; i < 1024; i += 256)
        ((float4*)wp)[i] = ((const float4*)(Wproj + (size_t)h*32*128))[i];
    __syncthreads();
    int c  = tid & 127;
    int eg = tid >> 7;
    for (int ee = 0; ee < 16; ee++) {
        int e = eg*16 + ee;
        float a = 0.f;
#pragma unroll
        for (int d = 0; d < 32; d++) a += as[d*33 + e] * wp[d*128 + c];
        g_M[(size_t)b*16384 + (h*32 + e)*128 + c] = a;
    }
}

// ---------------- fused Gabor (separable) + GELU + pointwise (tf32 mma) -----
// words: vt 6272 | ts 3696 | gs_t 32*132=4224 | pws_t 32*132=4224
#define GB_VT 6272
#define GB_TS 3696
#define LDGT 132
#define GB_TOTW (GB_VT + GB_TS + 32*LDGT + 32*LDGT)

__global__ void __launch_bounds__(256) gabor_kernel(const float* __restrict__ dw_w,
                                                    const float* __restrict__ dw_b,
                                                    const float* __restrict__ pw_w,
                                                    const float* __restrict__ pw_b,
                                                    float* __restrict__ out)
{
    extern __shared__ float smf[];
    float* vt = smf;
    float* ts = smf + GB_VT;
    uint32_t* gs_t  = (uint32_t*)(smf + GB_VT + GB_TS);
    uint32_t* pws_t = gs_t + 32*LDGT;

    int b  = blockIdx.z;
    int y0 = blockIdx.y << 3;
    int x0 = blockIdx.x << 3;
    int tid = threadIdx.x;
    int lane = tid & 31, warp = tid >> 5;
    int pq = lane >> 2;
    int kq = lane & 3;
    int wn = warp * 16;

    float acc[4][2][4];
#pragma unroll
    for (int mt = 0; mt < 4; mt++)
#pragma unroll
        for (int nt = 0; nt < 2; nt++)
#pragma unroll
            for (int r = 0; r < 4; r++) acc[mt][nt][r] = 0.f;

    for (int cg = 0; cg < 4; cg++) {
        int c0 = cg << 5;
        __syncthreads();
        {   // load v halo tile [14][14][32]
            int c = tid & 31;
            for (int p = tid >> 5; p < 196; p += 8) {
                int row = p / 14, col = p % 14;
                int gy = y0 - 3 + row, gx = x0 - 3 + col;
                float val = 0.f;
                if ((unsigned)gy < 256u && (unsigned)gx < 256u)
                    val = g_v[((size_t)(b*HW_ + gy*256 + gx))*128 + c0 + c];
                vt[(row*14 + col)*32 + c] = val;
            }
        }
        for (int s = 0; s < 4; s++) {
            __syncthreads();
            {   // horizontal pass
                float Bf[7];
#pragma unroll
                for (int j = 0; j < 7; j++) Bf[j] = dw_w[s*49 + 28 + j];
                int c = tid & 31;
                for (int rx = tid >> 5; rx < 112; rx += 8) {
                    int row = rx >> 3, xx = rx & 7;
                    float sum = 0.f;
#pragma unroll
                    for (int j = 0; j < 7; j++) sum += Bf[j]*vt[(row*14 + xx + j)*32 + c];
                    ts[rx*33 + c] = sum;
                }
            }
            {   // stage pointwise weights k-major permuted: pws_t[cc][perm(o)]
                int o = tid >> 1, cc0 = (tid & 1) << 4;
                int po = ((o & 7) << 4) + (o >> 3);
#pragma unroll 4
                for (int q = 0; q < 16; q++) {
                    int cc = cc0 + q;
                    pws_t[cc*LDGT + po] = f2tf(pw_w[(size_t)o*512 + (c0+cc)*4 + s]);
                }
            }
            __syncthreads();
            {   // vertical pass + bias + exact GELU -> gs_t[cc][perm(pix)]
                float Af[7];
#pragma unroll
                for (int i = 0; i < 7; i++) Af[i] = dw_w[s*49 + i*7 + 4];
                int c = tid & 31;
                int rbase = tid >> 5;   // xx
                float bias = dw_b[(c0+c)*4 + s];
                uint32_t gres[8];
#pragma unroll
                for (int i = 0; i < 8; i++) {   // y = i, xx = rbase
                    float sum = bias;
#pragma unroll
                    for (int t7 = 0; t7 < 7; t7++)
                        sum += Af[t7]*ts[((i+t7)*8 + rbase)*33 + c];
                    float g = 0.5f*sum*(1.f + erff(sum*0.70710678118654752f));
                    gres[i] = f2tf(g);
                }
                *(uint4*)&gs_t[c*LDGT + rbase*16]     = make_uint4(gres[0],gres[1],gres[2],gres[3]);
                *(uint4*)&gs_t[c*LDGT + rbase*16 + 4] = make_uint4(gres[4],gres[5],gres[6],gres[7]);
            }
            __syncthreads();
            // pointwise via mma: C[64 pix][128 out] += g[64][32k] * pw
#pragma unroll
            for (int ks = 0; ks < 32; ks += 8) {
                int ar = ks + kq;
                uint4 G0 = *(const uint4*)&gs_t[ar*LDGT     + pq*16];
                uint4 G1 = *(const uint4*)&gs_t[ar*LDGT     + pq*16 + 4];
                uint4 G4 = *(const uint4*)&gs_t[(ar+4)*LDGT + pq*16];
                uint4 G5 = *(const uint4*)&gs_t[(ar+4)*LDGT + pq*16 + 4];
                uint2 P0 = *(const uint2*)&pws_t[ar*LDGT     + pq*16 + 2*warp];
                uint2 P4 = *(const uint2*)&pws_t[(ar+4)*LDGT + pq*16 + 2*warp];
                uint32_t a[4][4] = {
                    {G0.x, G0.y, G4.x, G4.y},
                    {G0.z, G0.w, G4.z, G4.w},
                    {G1.x, G1.y, G5.x, G5.y},
                    {G1.z, G1.w, G5.z, G5.w}};
#pragma unroll
                for (int mt = 0; mt < 4; mt++) {
                    mma8(acc[mt][0], a[mt][0],a[mt][1],a[mt][2],a[mt][3], P0.x, P4.x);
                    mma8(acc[mt][1], a[mt][0],a[mt][1],a[mt][2],a[mt][3], P0.y, P4.y);
                }
            }
        }
    }
    // epilogue: WRITE out (first writer) = out_p + pw_b
#pragma unroll
    for (int mt = 0; mt < 4; mt++) {
#pragma unroll
        for (int nt = 0; nt < 2; nt++) {
            int c = wn + nt*8 + kq*2;
            float pb0 = pw_b[c], pb1 = pw_b[c+1];
#pragma unroll
            for (int half = 0; half < 2; half++) {
                int pix = mt*16 + pq + half*8;
                int y = pix >> 3, xx = pix & 7;
                size_t base = ((size_t)(b*HW_ + (y0+y)*256 + x0+xx))*128 + c;
                float2 o0;
                o0.x = acc[mt][nt][half*2+0] + pb0;
                o0.y = acc[mt][nt][half*2+1] + pb1;
                *(float2*)(out + base) = o0;
            }
        }
    }
}

// ---------------------------------------------------------------------------
extern "C" void kernel_launch(void* const* d_in, const int* in_sizes, int n_in,
                              void* d_out, int out_size)
{
    const float* x       = (const float*)d_in[0];
    const float* Wq      = (const float*)d_in[1];
    const float* Wk      = (const float*)d_in[2];
    const float* Wv      = (const float*)d_in[3];
    const float* rescale = (const float*)d_in[4];
    const float* Wproj   = (const float*)d_in[5];
    const float* bproj   = (const float*)d_in[6];
    const float* dw_w    = (const float*)d_in[7];
    const float* dw_b    = (const float*)d_in[8];
    const float* pw_w    = (const float*)d_in[9];
    const float* pw_b    = (const float*)d_in[10];
    float* out = (float*)d_out;

    cudaFuncSetAttribute(qkv_kernel, cudaFuncAttributeMaxDynamicSharedMemorySize, GEMM_SMEM);
    cudaFuncSetAttribute(vm_kernel,  cudaFuncAttributeMaxDynamicSharedMemorySize, GEMM_SMEM);
    cudaFuncSetAttribute(gabor_kernel, cudaFuncAttributeMaxDynamicSharedMemorySize,
                         GB_TOTW * (int)sizeof(float));

    zero_kernel<<<64, 256>>>();
    qkv_kernel<<<NTOK/128, 256, GEMM_SMEM>>>(x, Wq, Wk, Wv);
    attn_kernel<<<dim3(NCHUNK, HEADS_, B_), 256>>>();
    gabor_kernel<<<dim3(32, 32, B_), 256, GB_TOTW * sizeof(float)>>>(
        dw_w, dw_b, pw_w, pw_b, out);
    softmax_kernel<<<B_*HEADS_, 1024>>>(rescale);
    m_kernel<<<B_*HEADS_, 256>>>(Wproj);
    vm_kernel<<<NTOK/128, 256, GEMM_SMEM>>>(bproj, out);
}

// round 6
// speedup vs baseline: 3.6366x; 2.4293x over previous
#include <cuda_runtime.h>
#include <cuda_fp16.h>
#include <math.h>
#include <stdint.h>

#define B_ 4
#define HW_ 65536
#define NTOK (B_*HW_)
#define DIM_ 128
#define HEADS_ 4

__device__ __half g_q[(size_t)NTOK*DIM_];
__device__ __half g_k[(size_t)NTOK*DIM_];
__device__ __half g_v[(size_t)NTOK*DIM_];
__device__ float  g_attn[B_*HEADS_*32*32];
__device__ float  g_attn_sm[B_*HEADS_*32*32];
__device__ float  g_ssq[B_*HEADS_*32];
__device__ float  g_ssk[B_*HEADS_*32];
__device__ __half g_M[B_*DIM_*DIM_];
__device__ __half g_pwh[4*128*128];   // [s][o][c]

__device__ __forceinline__ uint32_t pack2(float a, float b) {
    __half2 h = __floats2half2_rn(a, b);
    return *(uint32_t*)&h;
}
__device__ __forceinline__ void mma16(float* c, const uint32_t* a, uint32_t b0, uint32_t b1) {
    asm volatile(
        "mma.sync.aligned.m16n8k16.row.col.f32.f16.f16.f32 "
        "{%0,%1,%2,%3},{%4,%5,%6,%7},{%8,%9},{%0,%1,%2,%3};"
        : "+f"(c[0]), "+f"(c[1]), "+f"(c[2]), "+f"(c[3])
        : "r"(a[0]), "r"(a[1]), "r"(a[2]), "r"(a[3]), "r"(b0), "r"(b1));
}
__device__ __forceinline__ void ldsm4(uint32_t* r, const __half* p) {
    uint32_t a = (uint32_t)__cvta_generic_to_shared(p);
    asm volatile("ldmatrix.sync.aligned.m8n8.x4.shared.b16 {%0,%1,%2,%3},[%4];"
                 : "=r"(r[0]), "=r"(r[1]), "=r"(r[2]), "=r"(r[3]) : "r"(a));
}
__device__ __forceinline__ void ldsm4t(uint32_t* r, const __half* p) {
    uint32_t a = (uint32_t)__cvta_generic_to_shared(p);
    asm volatile("ldmatrix.sync.aligned.m8n8.x4.trans.shared.b16 {%0,%1,%2,%3},[%4];"
                 : "=r"(r[0]), "=r"(r[1]), "=r"(r[2]), "=r"(r[3]) : "r"(a));
}

__global__ void zero_kernel() {
    int i = blockIdx.x*blockDim.x + threadIdx.x;
    if (i < B_*HEADS_*32*32) g_attn[i] = 0.f;
    if (i < B_*HEADS_*32) { g_ssq[i] = 0.f; g_ssk[i] = 0.f; }
}
__global__ void pw_prep_kernel(const float* __restrict__ pw_w) {
    int i = blockIdx.x*blockDim.x + threadIdx.x;   // 65536
    int c = i & 127, o = (i >> 7) & 127, s = i >> 14;
    g_pwh[(s*128 + o)*128 + c] = __float2half(pw_w[(size_t)o*512 + c*4 + s]);
}

// ======================= fp16 GEMM (X resident, W streamed) ==================
#define LDX 136
template<bool BHALF, bool OUTHALF>
__device__ __forceinline__ void gemm_pass_h(const __half* Xs, __half* Ws,
                                            const float* Wf, const __half* Wh,
                                            __half* OutH, float* OutF,
                                            const float* bias)
{
    int tid = threadIdx.x, lane = tid & 31, warp = tid >> 5;
    int wm = (warp & 3) * 32, wn = (warp >> 2) * 64;
    int mat = lane >> 3, rr = lane & 7;
    int arow = (mat & 1)*8 + rr, acol8 = (mat >> 1)*8;
    float acc[2][8][4];
#pragma unroll
    for (int mt = 0; mt < 2; mt++)
#pragma unroll
        for (int nt = 0; nt < 8; nt++)
#pragma unroll
            for (int r = 0; r < 4; r++) acc[mt][nt][r] = 0.f;

    int kk = tid >> 4, n0 = (tid & 15) << 3;
    uint4 wreg; float4 w0, w1;
    if (BHALF) wreg = *(const uint4*)(Wh + kk*128 + n0);
    else { w0 = *(const float4*)(Wf + kk*128 + n0); w1 = *(const float4*)(Wf + kk*128 + n0 + 4); }

    for (int c = 0; c < 8; c++) {
        if (BHALF) *(uint4*)(Ws + kk*LDX + n0) = wreg;
        else *(uint4*)(Ws + kk*LDX + n0) =
            make_uint4(pack2(w0.x,w0.y), pack2(w0.z,w0.w), pack2(w1.x,w1.y), pack2(w1.z,w1.w));
        __syncthreads();
        if (c < 7) {
            if (BHALF) wreg = *(const uint4*)(Wh + (c+1)*2048 + kk*128 + n0);
            else { w0 = *(const float4*)(Wf + (c+1)*2048 + kk*128 + n0);
                   w1 = *(const float4*)(Wf + (c+1)*2048 + kk*128 + n0 + 4); }
        }
        int k0 = c * 16;
        uint32_t a[2][4];
        ldsm4(a[0], Xs + (wm +      arow)*LDX + k0 + acol8);
        ldsm4(a[1], Xs + (wm + 16 + arow)*LDX + k0 + acol8);
        uint32_t b[8][2];
#pragma unroll
        for (int np = 0; np < 4; np++) {
            uint32_t r[4];
            ldsm4t(r, Ws + arow*LDX + wn + np*16 + acol8);
            b[np*2][0]=r[0]; b[np*2][1]=r[1]; b[np*2+1][0]=r[2]; b[np*2+1][1]=r[3];
        }
#pragma unroll
        for (int mt = 0; mt < 2; mt++)
#pragma unroll
            for (int nt = 0; nt < 8; nt++)
                mma16(acc[mt][nt], a[mt], b[nt][0], b[nt][1]);
        __syncthreads();
    }
    int g = lane >> 2, kq = lane & 3;
#pragma unroll
    for (int mt = 0; mt < 2; mt++)
#pragma unroll
        for (int nt = 0; nt < 8; nt++) {
            int r = wm + mt*16 + g, cc = wn + nt*8 + kq*2;
            if (OUTHALF) {
                *(uint32_t*)(OutH + (size_t)r*128 + cc)     = pack2(acc[mt][nt][0], acc[mt][nt][1]);
                *(uint32_t*)(OutH + (size_t)(r+8)*128 + cc) = pack2(acc[mt][nt][2], acc[mt][nt][3]);
            } else {
                float b0v = bias[cc], b1v = bias[cc+1];
                float2 o0 = *(float2*)(OutF + (size_t)r*128 + cc);
                float2 o1 = *(float2*)(OutF + (size_t)(r+8)*128 + cc);
                o0.x += acc[mt][nt][0] + b0v; o0.y += acc[mt][nt][1] + b1v;
                o1.x += acc[mt][nt][2] + b0v; o1.y += acc[mt][nt][3] + b1v;
                *(float2*)(OutF + (size_t)r*128 + cc)     = o0;
                *(float2*)(OutF + (size_t)(r+8)*128 + cc) = o1;
            }
        }
}
#define GEMM_SMEM ((128*LDX + 16*LDX)*2)

__global__ void __launch_bounds__(256) qkv_kernel(const float* __restrict__ x,
                                                  const float* __restrict__ Wq,
                                                  const float* __restrict__ Wk,
                                                  const float* __restrict__ Wv)
{
    extern __shared__ __half smh[];
    __half* Xs = smh; __half* Ws = smh + 128*LDX;
    int tid = threadIdx.x;
    size_t tok0 = (size_t)blockIdx.x * 128;
    int t2 = tid >> 1, kh = (tid & 1) * 64;
    const float* src = x + (tok0 + t2)*128 + kh;
    __half* dst = Xs + t2*LDX + kh;
#pragma unroll
    for (int i = 0; i < 8; i++) {
        float4 a = *(const float4*)(src + i*8);
        float4 b = *(const float4*)(src + i*8 + 4);
        *(uint4*)(dst + i*8) = make_uint4(pack2(a.x,a.y), pack2(a.z,a.w),
                                          pack2(b.x,b.y), pack2(b.z,b.w));
    }
    __syncthreads();
    gemm_pass_h<false,true>(Xs, Ws, Wq, nullptr, g_q + tok0*128, nullptr, nullptr);
    gemm_pass_h<false,true>(Xs, Ws, Wk, nullptr, g_k + tok0*128, nullptr, nullptr);
    gemm_pass_h<false,true>(Xs, Ws, Wv, nullptr, g_v + tok0*128, nullptr, nullptr);
}

__global__ void __launch_bounds__(256) vm_kernel(const float* __restrict__ bproj,
                                                 float* __restrict__ out)
{
    extern __shared__ __half smh[];
    __half* Xs = smh; __half* Ws = smh + 128*LDX;
    int tid = threadIdx.x;
    size_t tok0 = (size_t)blockIdx.x * 128;
    int b = blockIdx.x >> 9;
    int t2 = tid >> 1, kh = (tid & 1) * 64;
    const __half* src = g_v + (tok0 + t2)*128 + kh;
    __half* dst = Xs + t2*LDX + kh;
#pragma unroll
    for (int i = 0; i < 8; i++) *(uint4*)(dst + i*8) = *(const uint4*)(src + i*8);
    __syncthreads();
    gemm_pass_h<true,false>(Xs, Ws, nullptr, g_M + (size_t)b*16384,
                            nullptr, out + tok0*128, bproj);
}

// ======================= attn: attn[d,e] = sum_n k*q (fp16 mma) ==============
#define NCHUNK 16
#define LQH 40
__global__ void __launch_bounds__(256) attn_kernel()
{
    __shared__ __half qs[128*LQH];
    __shared__ __half ks[128*LQH];
    int b = blockIdx.z, h = blockIdx.y;
    int n0 = blockIdx.x * (HW_ / NCHUNK);
    int tid = threadIdx.x, lane = tid & 31, warp = tid >> 5;
    int mat = lane >> 3, rr = lane & 7;
    float acc[2][4][4];
#pragma unroll
    for (int mt = 0; mt < 2; mt++)
#pragma unroll
        for (int nt = 0; nt < 4; nt++)
#pragma unroll
            for (int r = 0; r < 4; r++) acc[mt][nt][r] = 0.f;
    float ssk_acc = 0.f, ssq_acc = 0.f;
    int kt = warp * 16;

    for (int sub = 0; sub < (HW_/NCHUNK)/128; sub++) {
        int t0 = n0 + sub*128;
        {
            int r = tid >> 1, off = (tid & 1) * 16;
            size_t base = ((size_t)(b*HW_ + t0 + r))*128 + h*32 + off;
            *(uint4*)(qs + r*LQH + off)     = *(const uint4*)(g_q + base);
            *(uint4*)(qs + r*LQH + off + 8) = *(const uint4*)(g_q + base + 8);
            *(uint4*)(ks + r*LQH + off)     = *(const uint4*)(g_k + base);
            *(uint4*)(ks + r*LQH + off + 8) = *(const uint4*)(g_k + base + 8);
        }
        __syncthreads();
        uint32_t a[2][4];
        ldsm4t(a[0], ks + (kt + (mat>>1)*8 + rr)*LQH + 0  + (mat&1)*8);
        ldsm4t(a[1], ks + (kt + (mat>>1)*8 + rr)*LQH + 16 + (mat&1)*8);
        uint32_t bfr[4][2];
#pragma unroll
        for (int eb = 0; eb < 2; eb++) {
            uint32_t r4[4];
            ldsm4t(r4, qs + (kt + (mat&1)*8 + rr)*LQH + eb*16 + (mat>>1)*8);
            bfr[eb*2][0]=r4[0]; bfr[eb*2][1]=r4[1]; bfr[eb*2+1][0]=r4[2]; bfr[eb*2+1][1]=r4[3];
        }
#pragma unroll
        for (int mt = 0; mt < 2; mt++)
#pragma unroll
            for (int nt = 0; nt < 4; nt++)
                mma16(acc[mt][nt], a[mt], bfr[nt][0], bfr[nt][1]);
#pragma unroll
        for (int tt = 0; tt < 16; tt++) {
            float kv = __half2float(ks[(kt+tt)*LQH + lane]);
            float qv = __half2float(qs[(kt+tt)*LQH + lane]);
            ssk_acc += kv*kv; ssq_acc += qv*qv;
        }
        __syncthreads();
    }
    int bh = b*HEADS_ + h;
    int g = lane >> 2, e0 = (lane & 3)*2;
#pragma unroll
    for (int mt = 0; mt < 2; mt++)
#pragma unroll
        for (int nt = 0; nt < 4; nt++) {
            int d = mt*16 + g, e = nt*8 + e0;
            atomicAdd(&g_attn[(bh*32 + d)*32 + e],       acc[mt][nt][0]);
            atomicAdd(&g_attn[(bh*32 + d)*32 + e + 1],   acc[mt][nt][1]);
            atomicAdd(&g_attn[(bh*32 + d+8)*32 + e],     acc[mt][nt][2]);
            atomicAdd(&g_attn[(bh*32 + d+8)*32 + e + 1], acc[mt][nt][3]);
        }
    atomicAdd(&g_ssk[bh*32 + lane], ssk_acc);
    atomicAdd(&g_ssq[bh*32 + lane], ssq_acc);
}

// ======================= softmax + M =========================================
__global__ void __launch_bounds__(1024) softmax_kernel(const float* __restrict__ rescale)
{
    int bh = blockIdx.x, h = bh & 3, tid = threadIdx.x;
    int d = tid >> 5, e = tid & 31;
    float nk = fmaxf(sqrtf(g_ssk[bh*32 + d]), 1e-12f);
    float nq = fmaxf(sqrtf(g_ssq[bh*32 + e]), 1e-12f);
    float val = g_attn[bh*1024 + d*32 + e] * rescale[h] / (nk*nq);
    float m = val;
#pragma unroll
    for (int off = 16; off > 0; off >>= 1) m = fmaxf(m, __shfl_xor_sync(~0u, m, off));
    float ex = expf(val - m);
    float s = ex;
#pragma unroll
    for (int off = 16; off > 0; off >>= 1) s += __shfl_xor_sync(~0u, s, off);
    g_attn_sm[bh*1024 + d*32 + e] = ex / s;
}

__global__ void __launch_bounds__(256) m_kernel(const float* __restrict__ Wproj)
{
    __shared__ float as[32*33];
    __shared__ float wp[32*128];
    int bh = blockIdx.x, b = bh >> 2, h = bh & 3, tid = threadIdx.x;
    for (int i = tid; i < 1024; i += 256) as[(i>>5)*33 + (i&31)] = g_attn_sm[bh*1024 + i];
    for (int i = tid; i < 1024; i += 256)
        ((float4*)wp)[i] = ((const float4*)(Wproj + (size_t)h*32*128))[i];
    __syncthreads();
    int c = tid & 127, eg = tid >> 7;
    for (int ee = 0; ee < 16; ee++) {
        int e = eg*16 + ee;
        float a = 0.f;
#pragma unroll
        for (int d = 0; d < 32; d++) a += as[d*33 + e] * wp[d*128 + c];
        g_M[(size_t)b*16384 + (h*32 + e)*128 + c] = __float2half(a);
    }
}

// ======================= Gabor: vert (hoisted) + per-s horiz/GELU + fp16 mma =
#define GB_VT 6272          // floats: 14*14*32
#define GB_TV 3584          // floats: 8*14*32
#define LDG 40
#define GB_BYTES (GB_VT*4 + GB_TV*4 + 64*LDG*2 + 128*LDG*2)

__global__ void __launch_bounds__(256) gabor_kernel(const float* __restrict__ dw_w,
                                                    const float* __restrict__ dw_b,
                                                    const float* __restrict__ pw_b,
                                                    float* __restrict__ out)
{
    extern __shared__ float smf[];
    float* vt = smf;
    float* tv = smf + GB_VT;
    __half* gh  = (__half*)(smf + GB_VT + GB_TV);
    __half* pws = gh + 64*LDG;

    int b  = blockIdx.z, y0 = blockIdx.y << 3, x0 = blockIdx.x << 3;
    int tid = threadIdx.x, lane = tid & 31, warp = tid >> 5;
    int mat = lane >> 3, rr = lane & 7;
    int wn = warp * 16;
    float acc[4][2][4];
#pragma unroll
    for (int mt = 0; mt < 4; mt++)
#pragma unroll
        for (int nt = 0; nt < 2; nt++)
#pragma unroll
            for (int r = 0; r < 4; r++) acc[mt][nt][r] = 0.f;

    float rowf[7];
#pragma unroll
    for (int i = 0; i < 7; i++) rowf[i] = dw_w[i*7 + 4];   // scale-independent

    for (int cg = 0; cg < 4; cg++) {
        int c0 = cg << 5;
        __syncthreads();
        {   // v halo tile [14][14][32] (half -> float)
            int c = tid & 31;
            for (int p = tid >> 5; p < 196; p += 8) {
                int row = p / 14, col = p % 14;
                int gy = y0 - 3 + row, gx = x0 - 3 + col;
                float val = 0.f;
                if ((unsigned)gy < 256u && (unsigned)gx < 256u)
                    val = __half2float(g_v[((size_t)(b*HW_ + gy*256 + gx))*128 + c0 + c]);
                vt[(row*14 + col)*32 + c] = val;
            }
        }
        __syncthreads();
        {   // vertical pass (scale-independent): tv[y][x14][c]
            int c = tid & 31;
            for (int p = tid >> 5; p < 112; p += 8) {
                int y = p / 14, xx = p % 14;
                float sum = 0.f;
#pragma unroll
                for (int i = 0; i < 7; i++) sum += rowf[i]*vt[((y+i)*14 + xx)*32 + c];
                tv[(y*14 + xx)*32 + c] = sum;
            }
        }
        for (int s = 0; s < 4; s++) {
            __syncthreads();
            {   // horizontal + bias + GELU -> gh half
                float colf[7];
#pragma unroll
                for (int j = 0; j < 7; j++) colf[j] = dw_w[s*49 + 28 + j];
                int c = tid & 31;
                float bias = dw_b[(c0+c)*4 + s];
                for (int p = tid >> 5; p < 64; p += 8) {
                    int y = p >> 3, xx = p & 7;
                    float sum = bias;
#pragma unroll
                    for (int j = 0; j < 7; j++) sum += colf[j]*tv[(y*14 + xx + j)*32 + c];
                    float g = 0.5f*sum*(1.f + erff(sum*0.70710678f));
                    gh[p*LDG + c] = __float2half(g);
                }
            }
            {   // stage pw (coalesced from prepped global): pws[o][c]
                int o = tid >> 1, off = (tid & 1)*16;
                const __half* src = g_pwh + ((s*128 + o)*128) + c0 + off;
                *(uint4*)(pws + o*LDG + off)     = *(const uint4*)src;
                *(uint4*)(pws + o*LDG + off + 8) = *(const uint4*)(src + 8);
            }
            __syncthreads();
#pragma unroll
            for (int kc = 0; kc < 2; kc++) {
                int k0 = kc*16;
                uint32_t a[4][4];
#pragma unroll
                for (int mt = 0; mt < 4; mt++)
                    ldsm4(a[mt], gh + (mt*16 + (mat&1)*8 + rr)*LDG + k0 + (mat>>1)*8);
                uint32_t r4[4];
                ldsm4(r4, pws + (wn + (mat>>1)*8 + rr)*LDG + k0 + (mat&1)*8);
#pragma unroll
                for (int mt = 0; mt < 4; mt++) {
                    mma16(acc[mt][0], a[mt], r4[0], r4[1]);
                    mma16(acc[mt][1], a[mt], r4[2], r4[3]);
                }
            }
        }
    }
    int g = lane >> 2, kq = lane & 3;
#pragma unroll
    for (int mt = 0; mt < 4; mt++)
#pragma unroll
        for (int nt = 0; nt < 2; nt++) {
            int c = wn + nt*8 + kq*2;
            float pb0 = pw_b[c], pb1 = pw_b[c+1];
#pragma unroll
            for (int half = 0; half < 2; half++) {
                int pix = mt*16 + g + half*8;
                int y = pix >> 3, xx = pix & 7;
                size_t base = ((size_t)(b*HW_ + (y0+y)*256 + x0+xx))*128 + c;
                float2 o0;
                o0.x = acc[mt][nt][half*2+0] + pb0;
                o0.y = acc[mt][nt][half*2+1] + pb1;
                *(float2*)(out + base) = o0;
            }
        }
}

// ---------------------------------------------------------------------------
extern "C" void kernel_launch(void* const* d_in, const int* in_sizes, int n_in,
                              void* d_out, int out_size)
{
    const float* x       = (const float*)d_in[0];
    const float* Wq      = (const float*)d_in[1];
    const float* Wk      = (const float*)d_in[2];
    const float* Wv      = (const float*)d_in[3];
    const float* rescale = (const float*)d_in[4];
    const float* Wproj   = (const float*)d_in[5];
    const float* bproj   = (const float*)d_in[6];
    const float* dw_w    = (const float*)d_in[7];
    const float* dw_b    = (const float*)d_in[8];
    const float* pw_w    = (const float*)d_in[9];
    const float* pw_b    = (const float*)d_in[10];
    float* out = (float*)d_out;

    cudaFuncSetAttribute(qkv_kernel, cudaFuncAttributeMaxDynamicSharedMemorySize, GEMM_SMEM);
    cudaFuncSetAttribute(vm_kernel,  cudaFuncAttributeMaxDynamicSharedMemorySize, GEMM_SMEM);
    cudaFuncSetAttribute(gabor_kernel, cudaFuncAttributeMaxDynamicSharedMemorySize, GB_BYTES);

    zero_kernel<<<64, 256>>>();
    pw_prep_kernel<<<256, 256>>>(pw_w);
    qkv_kernel<<<NTOK/128, 256, GEMM_SMEM>>>(x, Wq, Wk, Wv);
    attn_kernel<<<dim3(NCHUNK, HEADS_, B_), 256>>>();
    gabor_kernel<<<dim3(32, 32, B_), 256, GB_BYTES>>>(dw_w, dw_b, pw_b, out);
    softmax_kernel<<<B_*HEADS_, 1024>>>(rescale);
    m_kernel<<<B_*HEADS_, 256>>>(Wproj);
    vm_kernel<<<NTOK/128, 256, GEMM_SMEM>>>(bproj, out);
}